// round 2
// baseline (speedup 1.0000x reference)
#include <cuda_runtime.h>
#include <math.h>

#define Bv   4
#define Nv   256
#define CIN  256
#define CH   128
#define Wv   256
#define Hv   256
#define HW   (Wv*Hv)
#define Sv   256

// ---------------- scratch (static device allocations; no cudaMalloc) -------
__device__ float g_nf[Bv*Nv*CH];                 // normalized node features
__device__ float g_worldR[Bv*Nv*3];              // R_l2w @ (Kinv@[u,v,1] * depth)
__device__ float g_sfn[(size_t)Bv*HW*CH];        // normalized sat features, [b][pix][c]
__device__ float g_cand[Bv*Sv*Nv*2];             // candidate pixel coords
__device__ float g_logits[Bv*Sv];

// ---------------- f32x2 packed-FMA helpers (sm_103a FFMA2) -----------------
__device__ __forceinline__ unsigned long long pack2(float x, float y) {
    unsigned long long r;
    asm("mov.b64 %0, {%1, %2};" : "=l"(r) : "f"(x), "f"(y));
    return r;
}
__device__ __forceinline__ float2 unpack2(unsigned long long v) {
    float2 r;
    asm("mov.b64 {%0, %1}, %2;" : "=f"(r.x), "=f"(r.y) : "l"(v));
    return r;
}
#define FMA2(acc, a, b) asm("fma.rn.f32x2 %0, %1, %2, %0;" : "+l"(acc) : "l"(a), "l"(b))

// ---------------- K1: nf = normalize(node_features @ W_node + b_node) ------
__global__ void k_nf(const float* __restrict__ nfeat,
                     const float* __restrict__ Wn,
                     const float* __restrict__ bn) {
    __shared__ float sf[8][CIN];
    __shared__ float red[8][128];
    __shared__ float sinv[8];
    int t = threadIdx.x;                // 128 threads
    int cid = blockIdx.x;               // 0..127 (B*N/8)
    int b = cid >> 5;
    int n0 = (cid & 31) * 8;
    const float* src = nfeat + ((size_t)(b * Nv + n0)) * CIN;
    #pragma unroll
    for (int r = 0; r < 16; r++) {
        int idx = r * 128 + t;
        sf[idx >> 8][idx & 255] = src[idx];
    }
    __syncthreads();
    float acc[8];
    float bj = bn[t];
    #pragma unroll
    for (int i = 0; i < 8; i++) acc[i] = bj;
    for (int k = 0; k < CIN; k++) {
        float w = Wn[k * CH + t];
        #pragma unroll
        for (int i = 0; i < 8; i++) acc[i] += sf[i][k] * w;
    }
    #pragma unroll
    for (int i = 0; i < 8; i++) red[i][t] = acc[i] * acc[i];
    __syncthreads();
    if (t < 8) {
        float s = 0.f;
        for (int j = 0; j < 128; j++) s += red[t][j];
        sinv[t] = 1.0f / fmaxf(sqrtf(s), 1e-12f);
    }
    __syncthreads();
    #pragma unroll
    for (int i = 0; i < 8; i++)
        g_nf[(size_t)(b * Nv + n0 + i) * CH + t] = acc[i] * sinv[i];
}

// ---------------- K2: per-node world-space ray endpoints -------------------
__global__ void k_worldR(const float* __restrict__ coords,
                         const float* __restrict__ depths,
                         const float* __restrict__ Kl,
                         const float* __restrict__ Rl) {
    int idx = blockIdx.x * blockDim.x + threadIdx.x;
    if (idx >= Bv * Nv) return;
    int b = idx / Nv;
    const float* K = Kl + b * 9;
    float a00=K[0],a01=K[1],a02=K[2],a10=K[3],a11=K[4],a12=K[5],a20=K[6],a21=K[7],a22=K[8];
    float c00 = a11*a22 - a12*a21, c01 = a02*a21 - a01*a22, c02 = a01*a12 - a02*a11;
    float c10 = a12*a20 - a10*a22, c11 = a00*a22 - a02*a20, c12 = a02*a10 - a00*a12;
    float c20 = a10*a21 - a11*a20, c21 = a01*a20 - a00*a21, c22 = a00*a11 - a01*a10;
    float det = a00*c00 + a01*c10 + a02*c20;
    float id = 1.0f / det;
    float u = coords[idx*2+0], v = coords[idx*2+1];
    float d = depths[idx];
    float cx = (c00*u + c01*v + c02) * id * d;
    float cy = (c10*u + c11*v + c12) * id * d;
    float cz = (c20*u + c21*v + c22) * id * d;
    const float* R = Rl + b * 9;
    g_worldR[idx*3+0] = R[0]*cx + R[1]*cy + R[2]*cz;
    g_worldR[idx*3+1] = R[3]*cx + R[4]*cy + R[5]*cz;
    g_worldR[idx*3+2] = R[6]*cx + R[7]*cy + R[8]*cz;
}

// ---------------- K3: sf_norm GEMM  [HW x 256] @ [256 x 128], fused norm ---
__global__ __launch_bounds__(256) void k_sf(const float* __restrict__ feat,
                                            const float* __restrict__ Wsat,
                                            const float* __restrict__ bsat) {
    __shared__ float As[8][128];
    __shared__ float Bs[8][136];
    __shared__ float red[128 * 16];
    __shared__ float invp[128];
    int t  = threadIdx.x;
    int b  = blockIdx.y;
    int p0 = blockIdx.x * 128;
    int tx = t & 15, ty = t >> 4;
    int ox0 = tx * 8, py0 = ty * 8;
    const float* fb = feat + (size_t)b * CIN * HW + p0;

    unsigned long long accp[8][4];
    #pragma unroll
    for (int i = 0; i < 8; i++)
        #pragma unroll
        for (int m = 0; m < 4; m++) accp[i][m] = 0ull;

    int lk = t >> 5, lp = (t & 31) * 4;       // A-tile load indices
    int wo = t >> 1, wh = (t & 1) * 4;        // B-tile load indices

    for (int k0 = 0; k0 < CIN; k0 += 8) {
        float4 fa = *(const float4*)(fb + (size_t)(k0 + lk) * HW + lp);
        float4 wb = *(const float4*)(Wsat + wo * CIN + k0 + wh);
        __syncthreads();
        *(float4*)&As[lk][lp] = fa;
        Bs[wh+0][wo] = wb.x; Bs[wh+1][wo] = wb.y;
        Bs[wh+2][wo] = wb.z; Bs[wh+3][wo] = wb.w;
        __syncthreads();
        #pragma unroll
        for (int kk = 0; kk < 8; kk++) {
            float4 a0 = *(const float4*)&As[kk][py0];
            float4 a1 = *(const float4*)&As[kk][py0 + 4];
            ulonglong2 bq0 = *(const ulonglong2*)&Bs[kk][ox0];
            ulonglong2 bq1 = *(const ulonglong2*)&Bs[kk][ox0 + 4];
            float av[8] = {a0.x, a0.y, a0.z, a0.w, a1.x, a1.y, a1.z, a1.w};
            #pragma unroll
            for (int i = 0; i < 8; i++) {
                unsigned long long ai = pack2(av[i], av[i]);
                FMA2(accp[i][0], ai, bq0.x);
                FMA2(accp[i][1], ai, bq0.y);
                FMA2(accp[i][2], ai, bq1.x);
                FMA2(accp[i][3], ai, bq1.y);
            }
        }
    }
    // unpack + bias
    float acc[8][8];
    #pragma unroll
    for (int i = 0; i < 8; i++)
        #pragma unroll
        for (int m = 0; m < 4; m++) {
            float2 u = unpack2(accp[i][m]);
            acc[i][2*m]   = u.x;
            acc[i][2*m+1] = u.y;
        }
    float bsv[8];
    #pragma unroll
    for (int j = 0; j < 8; j++) bsv[j] = bsat[ox0 + j];
    #pragma unroll
    for (int i = 0; i < 8; i++)
        #pragma unroll
        for (int j = 0; j < 8; j++) acc[i][j] += bsv[j];
    // fused channel-norm (across the 16 tx threads per pixel)
    __syncthreads();
    #pragma unroll
    for (int i = 0; i < 8; i++) {
        float ss = 0.f;
        #pragma unroll
        for (int j = 0; j < 8; j++) ss += acc[i][j] * acc[i][j];
        red[(py0 + i) * 16 + tx] = ss;
    }
    __syncthreads();
    if (t < 128) {
        float s = 0.f;
        #pragma unroll
        for (int x = 0; x < 16; x++) s += red[t * 16 + x];
        invp[t] = 1.0f / fmaxf(sqrtf(s), 1e-12f);
    }
    __syncthreads();
    #pragma unroll
    for (int i = 0; i < 8; i++) {
        float inv = invp[py0 + i];
        size_t base = ((size_t)b * HW + p0 + py0 + i) * CH + ox0;
        float4 o0 = make_float4(acc[i][0]*inv, acc[i][1]*inv, acc[i][2]*inv, acc[i][3]*inv);
        float4 o1 = make_float4(acc[i][4]*inv, acc[i][5]*inv, acc[i][6]*inv, acc[i][7]*inv);
        *(float4*)&g_sfn[base]     = o0;
        *(float4*)&g_sfn[base + 4] = o1;
    }
}

// ---------------- K4: per-(b,s) projection + bilinear dot + logits ---------
__global__ __launch_bounds__(256) void k_sample(const float* __restrict__ Ksat,
                                                const float* __restrict__ Rsat,
                                                const float* __restrict__ tsat,
                                                const float* __restrict__ tinit,
                                                const float* __restrict__ radius,
                                                const float* __restrict__ scores) {
    int s = blockIdx.x, b = blockIdx.y;
    int t = threadIdx.x;
    int w = t >> 5, lane = t & 31;
    __shared__ float warpsum[8];
    float Km[9], Rm[9];
    #pragma unroll
    for (int i = 0; i < 9; i++) { Km[i] = Ksat[b*9+i]; Rm[i] = Rsat[b*9+i]; }
    float tsx = tsat[b*3+0], tsy = tsat[b*3+1], tsz = tsat[b*3+2];
    float rad = radius[b];
    float stepx = -1.f + (float)(s & 15) * (2.f / 15.f);
    float stepy = -1.f + (float)(s >> 4) * (2.f / 15.f);
    float ctx = tinit[b*3+0] + stepx * rad;
    float cty = tinit[b*3+1] + stepy * rad;
    float ctz = tinit[b*3+2];

    float lacc = 0.f;
    for (int n = w; n < Nv; n += 8) {
        const float* wr = g_worldR + (b * Nv + n) * 3;
        float wx = wr[0] + ctx - tsx;
        float wy = wr[1] + cty - tsy;
        float wz = wr[2] + ctz - tsz;
        // cam = R^T v   (einsum 'bji,bsnj->bsni')
        float cxs = Rm[0]*wx + Rm[3]*wy + Rm[6]*wz;
        float cys = Rm[1]*wx + Rm[4]*wy + Rm[7]*wz;
        float czs = Rm[2]*wx + Rm[5]*wy + Rm[8]*wz;
        float uu = Km[0]*cxs + Km[1]*cys + Km[2]*czs;
        float vv = Km[3]*cxs + Km[4]*cys + Km[5]*czs;
        float ww = Km[6]*cxs + Km[7]*cys + Km[8]*czs;
        float candx = uu / ww, candy = vv / ww;
        if (lane == 0) {
            g_cand[((size_t)(b*Sv + s) * Nv + n) * 2 + 0] = candx;
            g_cand[((size_t)(b*Sv + s) * Nv + n) * 2 + 1] = candy;
        }
        float ncx = candx / 255.0f * 2.0f - 1.0f;
        float ncy = candy / 255.0f * 2.0f - 1.0f;
        float px = ((ncx + 1.f) * (float)Wv - 1.f) * 0.5f;
        float py = ((ncy + 1.f) * (float)Hv - 1.f) * 0.5f;
        float x0f = floorf(px), y0f = floorf(py);
        float wx1 = px - x0f, wx0v = 1.f - wx1;
        float wy1 = py - y0f, wy0v = 1.f - wy1;
        float4 nfv = *(const float4*)(g_nf + (size_t)(b * Nv + n) * CH + lane * 4);
        float cw[4] = {wy0v*wx0v, wy0v*wx1, wy1*wx0v, wy1*wx1};
        float xs[4] = {x0f, x0f + 1.f, x0f, x0f + 1.f};
        float ys[4] = {y0f, y0f, y0f + 1.f, y0f + 1.f};
        float nodeacc = 0.f;
        #pragma unroll
        for (int c = 0; c < 4; c++) {
            float xf = xs[c], yf = ys[c];
            bool valid = (xf >= 0.f) && (xf <= 255.f) && (yf >= 0.f) && (yf <= 255.f);
            if (valid) {
                int xi = (int)xf, yi = (int)yf;
                float4 sv = *(const float4*)(g_sfn +
                    ((size_t)b * HW + yi * Wv + xi) * CH + lane * 4);
                float d = nfv.x*sv.x + nfv.y*sv.y + nfv.z*sv.z + nfv.w*sv.w;
                nodeacc += cw[c] * d;
            }
        }
        lacc += scores[b * Nv + n] * nodeacc;
    }
    #pragma unroll
    for (int o = 16; o > 0; o >>= 1) lacc += __shfl_down_sync(0xffffffffu, lacc, o);
    if (lane == 0) warpsum[w] = lacc;
    __syncthreads();
    if (t == 0) {
        float s8 = 0.f;
        #pragma unroll
        for (int i = 0; i < 8; i++) s8 += warpsum[i];
        g_logits[b * Sv + s] = s8;
    }
}

// ---------------- K5: softmax, argmax, outputs -----------------------------
// out layout: [0,2048) match [B,N,2]; [2048,3072) valid [B,N];
//             [3072,6144) cand_t [B,S,3]; [6144,7168) scores [B,S]
__global__ void k_final(float* __restrict__ out,
                        const float* __restrict__ tinit,
                        const float* __restrict__ radius,
                        const float* __restrict__ lscale) {
    int b = blockIdx.x;
    int t = threadIdx.x;   // 256
    __shared__ float sred[256];
    __shared__ int bestI;
    float escale = expf(lscale[0]);
    float L = g_logits[b * Sv + t] * escale;
    sred[t] = L; __syncthreads();
    for (int o = 128; o > 0; o >>= 1) {
        if (t < o) sred[t] = fmaxf(sred[t], sred[t + o]);
        __syncthreads();
    }
    float m = sred[0];
    __syncthreads();
    float e = expf(L - m);
    sred[t] = e; __syncthreads();
    for (int o = 128; o > 0; o >>= 1) {
        if (t < o) sred[t] += sred[t + o];
        __syncthreads();
    }
    float Z = sred[0];
    out[6144 + b * Sv + t] = e / Z;
    if (t == 0) bestI = 1 << 30;
    __syncthreads();
    if (L == m) atomicMin(&bestI, t);
    __syncthreads();
    int bi = bestI;
    // match + valid (n = t)
    float mx = g_cand[((size_t)(b * Sv + bi) * Nv + t) * 2 + 0];
    float my = g_cand[((size_t)(b * Sv + bi) * Nv + t) * 2 + 1];
    out[(b * Nv + t) * 2 + 0] = mx;
    out[(b * Nv + t) * 2 + 1] = my;
    out[2048 + b * Nv + t] =
        (mx >= 0.f && mx < (float)Wv && my >= 0.f && my < (float)Hv) ? 1.f : 0.f;
    // cand_t (s = t)
    float rad = radius[b];
    float sx = -1.f + (float)(t & 15) * (2.f / 15.f);
    float sy = -1.f + (float)(t >> 4) * (2.f / 15.f);
    out[3072 + (b * Sv + t) * 3 + 0] = tinit[b*3+0] + sx * rad;
    out[3072 + (b * Sv + t) * 3 + 1] = tinit[b*3+1] + sy * rad;
    out[3072 + (b * Sv + t) * 3 + 2] = tinit[b*3+2];
}

// ---------------- launch ----------------------------------------------------
extern "C" void kernel_launch(void* const* d_in, const int* in_sizes, int n_in,
                              void* d_out, int out_size) {
    const float* node_coords   = (const float*)d_in[0];
    const float* node_scores   = (const float*)d_in[1];
    const float* node_features = (const float*)d_in[2];
    const float* node_depths   = (const float*)d_in[3];
    const float* K_left        = (const float*)d_in[4];
    const float* R_left        = (const float*)d_in[5];
    const float* t_init        = (const float*)d_in[6];
    const float* sat_featmap   = (const float*)d_in[7];
    const float* K_sat         = (const float*)d_in[8];
    const float* R_sat         = (const float*)d_in[9];
    const float* t_sat         = (const float*)d_in[10];
    const float* radius        = (const float*)d_in[11];
    // d_in[12] is search_steps (scalar int) when present; handle both layouts.
    int off = (n_in >= 18) ? 0 : -1;
    const float* W_node      = (const float*)d_in[13 + off];
    const float* b_node      = (const float*)d_in[14 + off];
    const float* W_sat       = (const float*)d_in[15 + off];
    const float* b_sat       = (const float*)d_in[16 + off];
    const float* logit_scale = (const float*)d_in[17 + off];
    float* out = (float*)d_out;

    k_nf<<<128, 128>>>(node_features, W_node, b_node);
    k_worldR<<<4, 256>>>(node_coords, node_depths, K_left, R_left);
    k_sf<<<dim3(512, Bv), 256>>>(sat_featmap, W_sat, b_sat);
    k_sample<<<dim3(Sv, Bv), 256>>>(K_sat, R_sat, t_sat, t_init, radius, node_scores);
    k_final<<<Bv, 256>>>(out, t_init, radius, logit_scale);
}

// round 4
// speedup vs baseline: 1.0084x; 1.0084x over previous
#include <cuda_runtime.h>
#include <math.h>

#define Bv   4
#define Nv   256
#define CIN  256
#define CH   128
#define Wv   256
#define Hv   256
#define HW   (Wv*Hv)
#define Sv   256

// ---------------- scratch (static device allocations; no cudaMalloc) -------
__device__ float g_nf[Bv*Nv*CH];                 // normalized node features
__device__ float g_worldR[Bv*Nv*3];              // R_l2w @ (Kinv@[u,v,1] * depth)
__device__ float g_sfn[(size_t)Bv*HW*CH];        // normalized sat features, [b][pix][c]
__device__ float g_cand[Bv*Sv*Nv*2];             // candidate pixel coords
__device__ float g_logits[Bv*Sv];

// ---------------- f32x2 packed-FMA helpers (sm_103a FFMA2) -----------------
__device__ __forceinline__ unsigned long long pack2(float x, float y) {
    unsigned long long r;
    asm("mov.b64 %0, {%1, %2};" : "=l"(r) : "f"(x), "f"(y));
    return r;
}
__device__ __forceinline__ float2 unpack2(unsigned long long v) {
    float2 r;
    asm("mov.b64 {%0, %1}, %2;" : "=f"(r.x), "=f"(r.y) : "l"(v));
    return r;
}
#define FMA2(acc, a, b) asm("fma.rn.f32x2 %0, %1, %2, %0;" : "+l"(acc) : "l"(a), "l"(b))

// ---------------- K1: nf = normalize(node_features @ W_node + b_node) ------
__global__ void k_nf(const float* __restrict__ nfeat,
                     const float* __restrict__ Wn,
                     const float* __restrict__ bn) {
    __shared__ float sf[8][CIN];
    __shared__ float red[8][128];
    __shared__ float sinv[8];
    int t = threadIdx.x;                // 128 threads
    int cid = blockIdx.x;               // 0..127 (B*N/8)
    int b = cid >> 5;
    int n0 = (cid & 31) * 8;
    const float* src = nfeat + ((size_t)(b * Nv + n0)) * CIN;
    #pragma unroll
    for (int r = 0; r < 16; r++) {
        int idx = r * 128 + t;
        sf[idx >> 8][idx & 255] = src[idx];
    }
    __syncthreads();
    float acc[8];
    float bj = bn[t];
    #pragma unroll
    for (int i = 0; i < 8; i++) acc[i] = bj;
    for (int k = 0; k < CIN; k++) {
        float w = Wn[k * CH + t];
        #pragma unroll
        for (int i = 0; i < 8; i++) acc[i] += sf[i][k] * w;
    }
    #pragma unroll
    for (int i = 0; i < 8; i++) red[i][t] = acc[i] * acc[i];
    __syncthreads();
    if (t < 8) {
        float s = 0.f;
        for (int j = 0; j < 128; j++) s += red[t][j];
        sinv[t] = 1.0f / fmaxf(sqrtf(s), 1e-12f);
    }
    __syncthreads();
    #pragma unroll
    for (int i = 0; i < 8; i++)
        g_nf[(size_t)(b * Nv + n0 + i) * CH + t] = acc[i] * sinv[i];
}

// ---------------- K2: per-node world-space ray endpoints -------------------
__global__ void k_worldR(const float* __restrict__ coords,
                         const float* __restrict__ depths,
                         const float* __restrict__ Kl,
                         const float* __restrict__ Rl) {
    int idx = blockIdx.x * blockDim.x + threadIdx.x;
    if (idx >= Bv * Nv) return;
    int b = idx / Nv;
    const float* K = Kl + b * 9;
    float a00=K[0],a01=K[1],a02=K[2],a10=K[3],a11=K[4],a12=K[5],a20=K[6],a21=K[7],a22=K[8];
    float c00 = a11*a22 - a12*a21, c01 = a02*a21 - a01*a22, c02 = a01*a12 - a02*a11;
    float c10 = a12*a20 - a10*a22, c11 = a00*a22 - a02*a20, c12 = a02*a10 - a00*a12;
    float c20 = a10*a21 - a11*a20, c21 = a01*a20 - a00*a21, c22 = a00*a11 - a01*a10;
    float det = a00*c00 + a01*c10 + a02*c20;
    float id = 1.0f / det;
    float u = coords[idx*2+0], v = coords[idx*2+1];
    float d = depths[idx];
    float cx = (c00*u + c01*v + c02) * id * d;
    float cy = (c10*u + c11*v + c12) * id * d;
    float cz = (c20*u + c21*v + c22) * id * d;
    const float* R = Rl + b * 9;
    g_worldR[idx*3+0] = R[0]*cx + R[1]*cy + R[2]*cz;
    g_worldR[idx*3+1] = R[3]*cx + R[4]*cy + R[5]*cz;
    g_worldR[idx*3+2] = R[6]*cx + R[7]*cy + R[8]*cz;
}

// ---------------- K3: sf_norm GEMM  [HW x 256] @ [256 x 128], fused norm ---
__global__ __launch_bounds__(256) void k_sf(const float* __restrict__ feat,
                                            const float* __restrict__ Wsat,
                                            const float* __restrict__ bsat) {
    __shared__ float As[8][128];
    __shared__ float Bs[8][136];
    __shared__ float red[128 * 16];
    __shared__ float invp[128];
    int t  = threadIdx.x;
    int b  = blockIdx.y;
    int p0 = blockIdx.x * 128;
    int tx = t & 15, ty = t >> 4;
    int ox0 = tx * 8, py0 = ty * 8;
    const float* fb = feat + (size_t)b * CIN * HW + p0;

    unsigned long long accp[8][4];
    #pragma unroll
    for (int i = 0; i < 8; i++)
        #pragma unroll
        for (int m = 0; m < 4; m++) accp[i][m] = 0ull;

    int lk = t >> 5, lp = (t & 31) * 4;       // A-tile load indices
    int wo = t >> 1, wh = (t & 1) * 4;        // B-tile load indices

    for (int k0 = 0; k0 < CIN; k0 += 8) {
        float4 fa = *(const float4*)(fb + (size_t)(k0 + lk) * HW + lp);
        float4 wb = *(const float4*)(Wsat + wo * CIN + k0 + wh);
        __syncthreads();
        *(float4*)&As[lk][lp] = fa;
        Bs[wh+0][wo] = wb.x; Bs[wh+1][wo] = wb.y;
        Bs[wh+2][wo] = wb.z; Bs[wh+3][wo] = wb.w;
        __syncthreads();
        #pragma unroll
        for (int kk = 0; kk < 8; kk++) {
            float4 a0 = *(const float4*)&As[kk][py0];
            float4 a1 = *(const float4*)&As[kk][py0 + 4];
            ulonglong2 bq0 = *(const ulonglong2*)&Bs[kk][ox0];
            ulonglong2 bq1 = *(const ulonglong2*)&Bs[kk][ox0 + 4];
            float av[8] = {a0.x, a0.y, a0.z, a0.w, a1.x, a1.y, a1.z, a1.w};
            #pragma unroll
            for (int i = 0; i < 8; i++) {
                unsigned long long ai = pack2(av[i], av[i]);
                FMA2(accp[i][0], ai, bq0.x);
                FMA2(accp[i][1], ai, bq0.y);
                FMA2(accp[i][2], ai, bq1.x);
                FMA2(accp[i][3], ai, bq1.y);
            }
        }
    }
    // unpack + bias
    float acc[8][8];
    #pragma unroll
    for (int i = 0; i < 8; i++)
        #pragma unroll
        for (int m = 0; m < 4; m++) {
            float2 u = unpack2(accp[i][m]);
            acc[i][2*m]   = u.x;
            acc[i][2*m+1] = u.y;
        }
    float bsv[8];
    #pragma unroll
    for (int j = 0; j < 8; j++) bsv[j] = bsat[ox0 + j];
    #pragma unroll
    for (int i = 0; i < 8; i++)
        #pragma unroll
        for (int j = 0; j < 8; j++) acc[i][j] += bsv[j];
    // fused channel-norm (across the 16 tx threads per pixel)
    __syncthreads();
    #pragma unroll
    for (int i = 0; i < 8; i++) {
        float ss = 0.f;
        #pragma unroll
        for (int j = 0; j < 8; j++) ss += acc[i][j] * acc[i][j];
        red[(py0 + i) * 16 + tx] = ss;
    }
    __syncthreads();
    if (t < 128) {
        float s = 0.f;
        #pragma unroll
        for (int x = 0; x < 16; x++) s += red[t * 16 + x];
        invp[t] = 1.0f / fmaxf(sqrtf(s), 1e-12f);
    }
    __syncthreads();
    #pragma unroll
    for (int i = 0; i < 8; i++) {
        float inv = invp[py0 + i];
        size_t base = ((size_t)b * HW + p0 + py0 + i) * CH + ox0;
        float4 o0 = make_float4(acc[i][0]*inv, acc[i][1]*inv, acc[i][2]*inv, acc[i][3]*inv);
        float4 o1 = make_float4(acc[i][4]*inv, acc[i][5]*inv, acc[i][6]*inv, acc[i][7]*inv);
        *(float4*)&g_sfn[base]     = o0;
        *(float4*)&g_sfn[base + 4] = o1;
    }
}

// ---------------- K4: per-(b,s) projection + bilinear dot + logits ---------
__global__ __launch_bounds__(256) void k_sample(const float* __restrict__ Ksat,
                                                const float* __restrict__ Rsat,
                                                const float* __restrict__ tsat,
                                                const float* __restrict__ tinit,
                                                const float* __restrict__ radius,
                                                const float* __restrict__ scores) {
    int s = blockIdx.x, b = blockIdx.y;
    int t = threadIdx.x;
    int w = t >> 5, lane = t & 31;
    __shared__ float warpsum[8];
    float Km[9], Rm[9];
    #pragma unroll
    for (int i = 0; i < 9; i++) { Km[i] = Ksat[b*9+i]; Rm[i] = Rsat[b*9+i]; }
    float tsx = tsat[b*3+0], tsy = tsat[b*3+1], tsz = tsat[b*3+2];
    float rad = radius[b];
    float stepx = -1.f + (float)(s & 15) * (2.f / 15.f);
    float stepy = -1.f + (float)(s >> 4) * (2.f / 15.f);
    float ctx = tinit[b*3+0] + stepx * rad;
    float cty = tinit[b*3+1] + stepy * rad;
    float ctz = tinit[b*3+2];

    float lacc = 0.f;
    for (int n = w; n < Nv; n += 8) {
        const float* wr = g_worldR + (b * Nv + n) * 3;
        float wx = wr[0] + ctx - tsx;
        float wy = wr[1] + cty - tsy;
        float wz = wr[2] + ctz - tsz;
        // cam = R^T v   (einsum 'bji,bsnj->bsni')
        float cxs = Rm[0]*wx + Rm[3]*wy + Rm[6]*wz;
        float cys = Rm[1]*wx + Rm[4]*wy + Rm[7]*wz;
        float czs = Rm[2]*wx + Rm[5]*wy + Rm[8]*wz;
        float uu = Km[0]*cxs + Km[1]*cys + Km[2]*czs;
        float vv = Km[3]*cxs + Km[4]*cys + Km[5]*czs;
        float ww = Km[6]*cxs + Km[7]*cys + Km[8]*czs;
        float candx = uu / ww, candy = vv / ww;
        if (lane == 0) {
            g_cand[((size_t)(b*Sv + s) * Nv + n) * 2 + 0] = candx;
            g_cand[((size_t)(b*Sv + s) * Nv + n) * 2 + 1] = candy;
        }
        float ncx = candx / 255.0f * 2.0f - 1.0f;
        float ncy = candy / 255.0f * 2.0f - 1.0f;
        float px = ((ncx + 1.f) * (float)Wv - 1.f) * 0.5f;
        float py = ((ncy + 1.f) * (float)Hv - 1.f) * 0.5f;
        float x0f = floorf(px), y0f = floorf(py);
        float wx1 = px - x0f, wx0v = 1.f - wx1;
        float wy1 = py - y0f, wy0v = 1.f - wy1;
        float4 nfv = *(const float4*)(g_nf + (size_t)(b * Nv + n) * CH + lane * 4);
        float cw[4] = {wy0v*wx0v, wy0v*wx1, wy1*wx0v, wy1*wx1};
        float xs[4] = {x0f, x0f + 1.f, x0f, x0f + 1.f};
        float ys[4] = {y0f, y0f, y0f + 1.f, y0f + 1.f};
        float nodeacc = 0.f;
        #pragma unroll
        for (int c = 0; c < 4; c++) {
            float xf = xs[c], yf = ys[c];
            bool valid = (xf >= 0.f) && (xf <= 255.f) && (yf >= 0.f) && (yf <= 255.f);
            if (valid) {
                int xi = (int)xf, yi = (int)yf;
                float4 sv = *(const float4*)(g_sfn +
                    ((size_t)b * HW + yi * Wv + xi) * CH + lane * 4);
                float d = nfv.x*sv.x + nfv.y*sv.y + nfv.z*sv.z + nfv.w*sv.w;
                nodeacc += cw[c] * d;
            }
        }
        lacc += scores[b * Nv + n] * nodeacc;
    }
    #pragma unroll
    for (int o = 16; o > 0; o >>= 1) lacc += __shfl_down_sync(0xffffffffu, lacc, o);
    if (lane == 0) warpsum[w] = lacc;
    __syncthreads();
    if (t == 0) {
        float s8 = 0.f;
        #pragma unroll
        for (int i = 0; i < 8; i++) s8 += warpsum[i];
        g_logits[b * Sv + s] = s8;
    }
}

// ---------------- K5: softmax, argmax, outputs -----------------------------
// out layout: [0,2048) match [B,N,2]; [2048,3072) valid [B,N];
//             [3072,6144) cand_t [B,S,3]; [6144,7168) scores [B,S]
__global__ void k_final(float* __restrict__ out,
                        const float* __restrict__ tinit,
                        const float* __restrict__ radius,
                        const float* __restrict__ lscale) {
    int b = blockIdx.x;
    int t = threadIdx.x;   // 256
    __shared__ float sred[256];
    __shared__ int bestI;
    float escale = expf(lscale[0]);
    float L = g_logits[b * Sv + t] * escale;
    sred[t] = L; __syncthreads();
    for (int o = 128; o > 0; o >>= 1) {
        if (t < o) sred[t] = fmaxf(sred[t], sred[t + o]);
        __syncthreads();
    }
    float m = sred[0];
    __syncthreads();
    float e = expf(L - m);
    sred[t] = e; __syncthreads();
    for (int o = 128; o > 0; o >>= 1) {
        if (t < o) sred[t] += sred[t + o];
        __syncthreads();
    }
    float Z = sred[0];
    out[6144 + b * Sv + t] = e / Z;
    if (t == 0) bestI = 1 << 30;
    __syncthreads();
    if (L == m) atomicMin(&bestI, t);
    __syncthreads();
    int bi = bestI;
    // match + valid (n = t)
    float mx = g_cand[((size_t)(b * Sv + bi) * Nv + t) * 2 + 0];
    float my = g_cand[((size_t)(b * Sv + bi) * Nv + t) * 2 + 1];
    out[(b * Nv + t) * 2 + 0] = mx;
    out[(b * Nv + t) * 2 + 1] = my;
    out[2048 + b * Nv + t] =
        (mx >= 0.f && mx < (float)Wv && my >= 0.f && my < (float)Hv) ? 1.f : 0.f;
    // cand_t (s = t)
    float rad = radius[b];
    float sx = -1.f + (float)(t & 15) * (2.f / 15.f);
    float sy = -1.f + (float)(t >> 4) * (2.f / 15.f);
    out[3072 + (b * Sv + t) * 3 + 0] = tinit[b*3+0] + sx * rad;
    out[3072 + (b * Sv + t) * 3 + 1] = tinit[b*3+1] + sy * rad;
    out[3072 + (b * Sv + t) * 3 + 2] = tinit[b*3+2];
}

// ---------------- launch ----------------------------------------------------
extern "C" void kernel_launch(void* const* d_in, const int* in_sizes, int n_in,
                              void* d_out, int out_size) {
    const float* node_coords   = (const float*)d_in[0];
    const float* node_scores   = (const float*)d_in[1];
    const float* node_features = (const float*)d_in[2];
    const float* node_depths   = (const float*)d_in[3];
    const float* K_left        = (const float*)d_in[4];
    const float* R_left        = (const float*)d_in[5];
    const float* t_init        = (const float*)d_in[6];
    const float* sat_featmap   = (const float*)d_in[7];
    const float* K_sat         = (const float*)d_in[8];
    const float* R_sat         = (const float*)d_in[9];
    const float* t_sat         = (const float*)d_in[10];
    const float* radius        = (const float*)d_in[11];
    // d_in[12] is search_steps (scalar int) when present; handle both layouts.
    int off = (n_in >= 18) ? 0 : -1;
    const float* W_node      = (const float*)d_in[13 + off];
    const float* b_node      = (const float*)d_in[14 + off];
    const float* W_sat       = (const float*)d_in[15 + off];
    const float* b_sat       = (const float*)d_in[16 + off];
    const float* logit_scale = (const float*)d_in[17 + off];
    float* out = (float*)d_out;

    k_nf<<<128, 128>>>(node_features, W_node, b_node);
    k_worldR<<<4, 256>>>(node_coords, node_depths, K_left, R_left);
    k_sf<<<dim3(512, Bv), 256>>>(sat_featmap, W_sat, b_sat);
    k_sample<<<dim3(Sv, Bv), 256>>>(K_sat, R_sat, t_sat, t_init, radius, node_scores);
    k_final<<<Bv, 256>>>(out, t_init, radius, logit_scale);
}

// round 7
// speedup vs baseline: 1.4337x; 1.4217x over previous
#include <cuda_runtime.h>
#include <cuda_bf16.h>
#include <math.h>
#include <stdint.h>

#define Bv   4
#define Nv   256
#define CIN  256
#define CH   128
#define Wv   256
#define Hv   256
#define HW   (Wv*Hv)
#define Sv   256

// ---------------- scratch ---------------------------------------------------
__device__ float g_nf[Bv*Nv*CH];
__device__ float g_worldR[Bv*Nv*3];
__device__ float g_sfn[(size_t)Bv*HW*CH];
__device__ float g_cand[Bv*Sv*Nv*2];
__device__ float g_logits[Bv*Sv];

// ---------------- helpers ---------------------------------------------------
__device__ __forceinline__ uint32_t s2u(const void* p){
    uint32_t a;
    asm("{ .reg .u64 t; cvta.to.shared.u64 t, %1; cvt.u32.u64 %0, t; }" : "=r"(a) : "l"(p));
    return a;
}
__device__ __forceinline__ uint32_t packbf(float lo_e, float hi_e){
    uint32_t r;   // lower 16 bits <- lo_e
    asm("cvt.rn.bf16x2.f32 %0, %1, %2;" : "=r"(r) : "f"(hi_e), "f"(lo_e));
    return r;
}
__device__ __forceinline__ float bfhi(float x){
    return __bfloat162float(__float2bfloat16_rn(x));
}
// convert 4 consecutive elements -> bf16 hi/lo, 8B each
__device__ __forceinline__ void cvt_store8(char* hp, char* lp, float4 v){
    float h0=bfhi(v.x), h1=bfhi(v.y), h2=bfhi(v.z), h3=bfhi(v.w);
    uint2 H = make_uint2(packbf(h0,h1), packbf(h2,h3));
    uint2 L = make_uint2(packbf(v.x-h0, v.y-h1), packbf(v.z-h2, v.w-h3));
    *(uint2*)hp = H;
    *(uint2*)lp = L;
}
__device__ __forceinline__ void ldsm4(uint32_t* r, uint32_t addr){
    asm volatile("ldmatrix.sync.aligned.m8n8.x4.shared.b16 {%0,%1,%2,%3}, [%4];"
        : "=r"(r[0]), "=r"(r[1]), "=r"(r[2]), "=r"(r[3]) : "r"(addr));
}
__device__ __forceinline__ void ldsm4t(uint32_t* r, uint32_t addr){
    asm volatile("ldmatrix.sync.aligned.m8n8.x4.trans.shared.b16 {%0,%1,%2,%3}, [%4];"
        : "=r"(r[0]), "=r"(r[1]), "=r"(r[2]), "=r"(r[3]) : "r"(addr));
}
__device__ __forceinline__ void mma16816(float* d, const uint32_t* a, const uint32_t* b){
    asm volatile("mma.sync.aligned.m16n8k16.row.col.f32.bf16.bf16.f32 "
        "{%0,%1,%2,%3}, {%4,%5,%6,%7}, {%8,%9}, {%0,%1,%2,%3};"
        : "+f"(d[0]), "+f"(d[1]), "+f"(d[2]), "+f"(d[3])
        : "r"(a[0]), "r"(a[1]), "r"(a[2]), "r"(a[3]), "r"(b[0]), "r"(b[1]));
}

// ---------------- K1: nf = normalize(node_features @ W_node + b_node) ------
__global__ void k_nf(const float* __restrict__ nfeat,
                     const float* __restrict__ Wn,
                     const float* __restrict__ bn) {
    __shared__ float sf[8][CIN];
    __shared__ float red[8][128];
    __shared__ float sinv[8];
    int t = threadIdx.x;
    int cid = blockIdx.x;
    int b = cid >> 5;
    int n0 = (cid & 31) * 8;
    const float* src = nfeat + ((size_t)(b * Nv + n0)) * CIN;
    #pragma unroll
    for (int r = 0; r < 16; r++) {
        int idx = r * 128 + t;
        sf[idx >> 8][idx & 255] = src[idx];
    }
    __syncthreads();
    float acc[8];
    float bj = bn[t];
    #pragma unroll
    for (int i = 0; i < 8; i++) acc[i] = bj;
    for (int k = 0; k < CIN; k++) {
        float w = Wn[k * CH + t];
        #pragma unroll
        for (int i = 0; i < 8; i++) acc[i] += sf[i][k] * w;
    }
    #pragma unroll
    for (int i = 0; i < 8; i++) red[i][t] = acc[i] * acc[i];
    __syncthreads();
    if (t < 8) {
        float s = 0.f;
        for (int j = 0; j < 128; j++) s += red[t][j];
        sinv[t] = 1.0f / fmaxf(sqrtf(s), 1e-12f);
    }
    __syncthreads();
    #pragma unroll
    for (int i = 0; i < 8; i++)
        g_nf[(size_t)(b * Nv + n0 + i) * CH + t] = acc[i] * sinv[i];
}

// ---------------- K2: per-node world-space ray endpoints -------------------
__global__ void k_worldR(const float* __restrict__ coords,
                         const float* __restrict__ depths,
                         const float* __restrict__ Kl,
                         const float* __restrict__ Rl) {
    int idx = blockIdx.x * blockDim.x + threadIdx.x;
    if (idx >= Bv * Nv) return;
    int b = idx / Nv;
    const float* K = Kl + b * 9;
    float a00=K[0],a01=K[1],a02=K[2],a10=K[3],a11=K[4],a12=K[5],a20=K[6],a21=K[7],a22=K[8];
    float c00 = a11*a22 - a12*a21, c01 = a02*a21 - a01*a22, c02 = a01*a12 - a02*a11;
    float c10 = a12*a20 - a10*a22, c11 = a00*a22 - a02*a20, c12 = a02*a10 - a00*a12;
    float c20 = a10*a21 - a11*a20, c21 = a01*a20 - a00*a21, c22 = a00*a11 - a01*a10;
    float det = a00*c00 + a01*c10 + a02*c20;
    float id = 1.0f / det;
    float u = coords[idx*2+0], v = coords[idx*2+1];
    float d = depths[idx];
    float cx = (c00*u + c01*v + c02) * id * d;
    float cy = (c10*u + c11*v + c12) * id * d;
    float cz = (c20*u + c21*v + c22) * id * d;
    const float* R = Rl + b * 9;
    g_worldR[idx*3+0] = R[0]*cx + R[1]*cy + R[2]*cz;
    g_worldR[idx*3+1] = R[3]*cx + R[4]*cy + R[5]*cz;
    g_worldR[idx*3+2] = R[6]*cx + R[7]*cy + R[8]*cz;
}

// ---------------- K3: sf_norm via mma.sync bf16-split ----------------------
// D[o=128][px=128] = sum_c W[o][c]*feat[c][px], K=256 in 4 chunks of 64.
// A = W row-major [o][c] (ldmatrix.x4), B = feat [c][px] (ldmatrix.x4.trans).
// 3-term bf16 split. 8 warps: warp_m = wid&3 (32 o), warp_n = wid>>2 (64 px).
// SMEM: WH[128][528B] WL[128][528B] (full W, hi/lo), feat double-buffered
// FH/FL[2][64][272B]. Total 204800 B dynamic.
#define WH_OFF 0
#define WL_OFF 67584
#define F_OFF  135168
#define FBUF   17408
#define A_PITCH 528
#define B_PITCH 272

__global__ __launch_bounds__(256) void k_sfmma(const float* __restrict__ feat,
                                               const float* __restrict__ Wsat,
                                               const float* __restrict__ bsat) {
    extern __shared__ char dsm[];
    __shared__ float s_inv[128];
    uint32_t sb = s2u(dsm);

    int t = threadIdx.x, wid = t >> 5, lane = t & 31;
    int warp_m = wid & 3, warp_n = wid >> 2;
    int b = blockIdx.y, p0 = blockIdx.x * 128;
    const float* fb = feat + (size_t)b * CIN * HW + p0;

    // ---- load full W (hi+lo) into SMEM --------------------------------------
    #pragma unroll 4
    for (int j = 0; j < 32; j++) {
        int idx = j * 256 + t;
        int o = idx >> 6, cg = idx & 63;
        float4 v = *(const float4*)(Wsat + o * CIN + cg * 4);
        cvt_store8(dsm + WH_OFF + o * A_PITCH + cg * 8,
                   dsm + WL_OFF + o * A_PITCH + cg * 8, v);
    }
    // ---- feat chunk 0 -> buffer 0 ------------------------------------------
    {
        #pragma unroll
        for (int j = 0; j < 8; j++) {
            int idx = j * 256 + t;
            int c = idx >> 5, pxg = idx & 31;
            float4 v = *(const float4*)(fb + (size_t)c * HW + pxg * 4);
            cvt_store8(dsm + F_OFF + 0 * FBUF * 2 + c * B_PITCH + pxg * 8,
                       dsm + F_OFF + 0 * FBUF * 2 + FBUF + c * B_PITCH + pxg * 8, v);
        }
    }
    __syncthreads();

    // per-thread ldmatrix address components
    uint32_t lrow = lane & 15;
    uint32_t lsel = (lane >> 4) & 1;
    uint32_t aRow = (uint32_t)(warp_m * 32 + lrow) * A_PITCH;
    uint32_t aCol = lsel * 16;                       // bytes
    uint32_t bRow = lrow * B_PITCH;
    uint32_t bCol = (uint32_t)(warp_n * 64 + lsel * 8) * 2;

    float acc[2][8][4];
    #pragma unroll
    for (int i = 0; i < 2; i++)
        #pragma unroll
        for (int j = 0; j < 8; j++)
            #pragma unroll
            for (int r = 0; r < 4; r++) acc[i][j][r] = 0.f;

    #pragma unroll
    for (int chunk = 0; chunk < 4; chunk++) {
        // prefetch next feat chunk
        float4 pre[8];
        if (chunk < 3) {
            #pragma unroll
            for (int j = 0; j < 8; j++) {
                int idx = j * 256 + t;
                int c = idx >> 5, pxg = idx & 31;
                pre[j] = *(const float4*)(fb + (size_t)((chunk + 1) * 64 + c) * HW + pxg * 4);
            }
        }
        uint32_t fh = sb + F_OFF + (uint32_t)(chunk & 1) * (FBUF * 2);
        uint32_t fl = fh + FBUF;
        #pragma unroll
        for (int ks = 0; ks < 4; ks++) {
            uint32_t ac = (uint32_t)(chunk * 64 + ks * 16) * 2 + aCol;
            uint32_t ah[2][4], al[2][4];
            ldsm4(ah[0], sb + WH_OFF + aRow + ac);
            ldsm4(ah[1], sb + WH_OFF + aRow + 16 * A_PITCH + ac);
            ldsm4(al[0], sb + WL_OFF + aRow + ac);
            ldsm4(al[1], sb + WL_OFF + aRow + 16 * A_PITCH + ac);
            #pragma unroll
            for (int nf2 = 0; nf2 < 4; nf2++) {
                uint32_t boff = bRow + (uint32_t)ks * (16 * B_PITCH) + bCol + (uint32_t)nf2 * 32;
                uint32_t bh[4], bl[4];
                ldsm4t(bh, fh + boff);
                ldsm4t(bl, fl + boff);
                #pragma unroll
                for (int fm = 0; fm < 2; fm++) {
                    mma16816(acc[fm][2*nf2],     ah[fm], bh + 0);
                    mma16816(acc[fm][2*nf2],     ah[fm], bl + 0);
                    mma16816(acc[fm][2*nf2],     al[fm], bh + 0);
                    mma16816(acc[fm][2*nf2 + 1], ah[fm], bh + 2);
                    mma16816(acc[fm][2*nf2 + 1], ah[fm], bl + 2);
                    mma16816(acc[fm][2*nf2 + 1], al[fm], bh + 2);
                }
            }
        }
        if (chunk < 3) {
            char* nh = dsm + F_OFF + (size_t)((chunk + 1) & 1) * (FBUF * 2);
            #pragma unroll
            for (int j = 0; j < 8; j++) {
                int idx = j * 256 + t;
                int c = idx >> 5, pxg = idx & 31;
                cvt_store8(nh + c * B_PITCH + pxg * 8,
                           nh + FBUF + c * B_PITCH + pxg * 8, pre[j]);
            }
            __syncthreads();
        }
    }
    __syncthreads();   // all mma done before reusing W region as stage

    // ---- epilogue: stage [px][o] (+bias), per-px L2 norm, coalesced store --
    float* stg = (float*)dsm;          // 128 px x 132 floats
    float bias0[2], bias1[2];
    #pragma unroll
    for (int fm = 0; fm < 2; fm++) {
        int m = warp_m * 32 + fm * 16 + (lane >> 2);
        bias0[fm] = bsat[m];
        bias1[fm] = bsat[m + 8];
    }
    #pragma unroll
    for (int fm = 0; fm < 2; fm++) {
        int m0 = warp_m * 32 + fm * 16 + (lane >> 2);
        #pragma unroll
        for (int fn = 0; fn < 8; fn++) {
            int n0 = warp_n * 64 + fn * 8 + (lane & 3) * 2;
            stg[n0 * 132 + m0]           = acc[fm][fn][0] + bias0[fm];
            stg[(n0 + 1) * 132 + m0]     = acc[fm][fn][1] + bias0[fm];
            stg[n0 * 132 + m0 + 8]       = acc[fm][fn][2] + bias1[fm];
            stg[(n0 + 1) * 132 + m0 + 8] = acc[fm][fn][3] + bias1[fm];
        }
    }
    __syncthreads();
    if (t < 128) {
        float ss = 0.f;
        #pragma unroll
        for (int o4 = 0; o4 < 32; o4++) {
            float4 v = *(const float4*)&stg[t * 132 + o4 * 4];
            ss += v.x*v.x + v.y*v.y + v.z*v.z + v.w*v.w;
        }
        s_inv[t] = 1.0f / fmaxf(sqrtf(ss), 1e-12f);
    }
    __syncthreads();
    float* outp = g_sfn + ((size_t)b * HW + p0) * CH;
    #pragma unroll
    for (int it = 0; it < 16; it++) {
        int idx = it * 256 + t;
        int px = idx >> 5, cg = idx & 31;
        float4 v = *(const float4*)&stg[px * 132 + cg * 4];
        float inv = s_inv[px];
        v.x *= inv; v.y *= inv; v.z *= inv; v.w *= inv;
        *(float4*)&outp[(size_t)px * CH + cg * 4] = v;
    }
}

// ---------------- K4: per-(b,s) projection + bilinear dot + logits ---------
__global__ __launch_bounds__(256) void k_sample(const float* __restrict__ Ksat,
                                                const float* __restrict__ Rsat,
                                                const float* __restrict__ tsat,
                                                const float* __restrict__ tinit,
                                                const float* __restrict__ radius,
                                                const float* __restrict__ scores) {
    int s = blockIdx.x, b = blockIdx.y;
    int t = threadIdx.x;
    int w = t >> 5, lane = t & 31;
    __shared__ float warpsum[8];
    float Km[9], Rm[9];
    #pragma unroll
    for (int i = 0; i < 9; i++) { Km[i] = Ksat[b*9+i]; Rm[i] = Rsat[b*9+i]; }
    float tsx = tsat[b*3+0], tsy = tsat[b*3+1], tsz = tsat[b*3+2];
    float rad = radius[b];
    float stepx = -1.f + (float)(s & 15) * (2.f / 15.f);
    float stepy = -1.f + (float)(s >> 4) * (2.f / 15.f);
    float ctx = tinit[b*3+0] + stepx * rad;
    float cty = tinit[b*3+1] + stepy * rad;
    float ctz = tinit[b*3+2];

    float lacc = 0.f;
    for (int n = w; n < Nv; n += 8) {
        const float* wr = g_worldR + (b * Nv + n) * 3;
        float wx = wr[0] + ctx - tsx;
        float wy = wr[1] + cty - tsy;
        float wz = wr[2] + ctz - tsz;
        float cxs = Rm[0]*wx + Rm[3]*wy + Rm[6]*wz;
        float cys = Rm[1]*wx + Rm[4]*wy + Rm[7]*wz;
        float czs = Rm[2]*wx + Rm[5]*wy + Rm[8]*wz;
        float uu = Km[0]*cxs + Km[1]*cys + Km[2]*czs;
        float vv = Km[3]*cxs + Km[4]*cys + Km[5]*czs;
        float ww = Km[6]*cxs + Km[7]*cys + Km[8]*czs;
        float candx = uu / ww, candy = vv / ww;
        if (lane == 0) {
            g_cand[((size_t)(b*Sv + s) * Nv + n) * 2 + 0] = candx;
            g_cand[((size_t)(b*Sv + s) * Nv + n) * 2 + 1] = candy;
        }
        float ncx = candx / 255.0f * 2.0f - 1.0f;
        float ncy = candy / 255.0f * 2.0f - 1.0f;
        float px = ((ncx + 1.f) * (float)Wv - 1.f) * 0.5f;
        float py = ((ncy + 1.f) * (float)Hv - 1.f) * 0.5f;
        float x0f = floorf(px), y0f = floorf(py);
        float wx1 = px - x0f, wx0v = 1.f - wx1;
        float wy1 = py - y0f, wy0v = 1.f - wy1;
        float4 nfv = *(const float4*)(g_nf + (size_t)(b * Nv + n) * CH + lane * 4);
        float cw[4] = {wy0v*wx0v, wy0v*wx1, wy1*wx0v, wy1*wx1};
        float xs[4] = {x0f, x0f + 1.f, x0f, x0f + 1.f};
        float ys[4] = {y0f, y0f, y0f + 1.f, y0f + 1.f};
        float nodeacc = 0.f;
        #pragma unroll
        for (int c = 0; c < 4; c++) {
            float xf = xs[c], yf = ys[c];
            bool valid = (xf >= 0.f) && (xf <= 255.f) && (yf >= 0.f) && (yf <= 255.f);
            if (valid) {
                int xi = (int)xf, yi = (int)yf;
                float4 sv = *(const float4*)(g_sfn +
                    ((size_t)b * HW + yi * Wv + xi) * CH + lane * 4);
                float d = nfv.x*sv.x + nfv.y*sv.y + nfv.z*sv.z + nfv.w*sv.w;
                nodeacc += cw[c] * d;
            }
        }
        lacc += scores[b * Nv + n] * nodeacc;
    }
    #pragma unroll
    for (int o = 16; o > 0; o >>= 1) lacc += __shfl_down_sync(0xffffffffu, lacc, o);
    if (lane == 0) warpsum[w] = lacc;
    __syncthreads();
    if (t == 0) {
        float s8 = 0.f;
        #pragma unroll
        for (int i = 0; i < 8; i++) s8 += warpsum[i];
        g_logits[b * Sv + s] = s8;
    }
}

// ---------------- K5: softmax, argmax, outputs -----------------------------
__global__ void k_final(float* __restrict__ out,
                        const float* __restrict__ tinit,
                        const float* __restrict__ radius,
                        const float* __restrict__ lscale) {
    int b = blockIdx.x;
    int t = threadIdx.x;   // 256
    __shared__ float sred[256];
    __shared__ int bestI;
    float escale = expf(lscale[0]);
    float L = g_logits[b * Sv + t] * escale;
    sred[t] = L; __syncthreads();
    for (int o = 128; o > 0; o >>= 1) {
        if (t < o) sred[t] = fmaxf(sred[t], sred[t + o]);
        __syncthreads();
    }
    float m = sred[0];
    __syncthreads();
    float e = expf(L - m);
    sred[t] = e; __syncthreads();
    for (int o = 128; o > 0; o >>= 1) {
        if (t < o) sred[t] += sred[t + o];
        __syncthreads();
    }
    float Z = sred[0];
    out[6144 + b * Sv + t] = e / Z;
    if (t == 0) bestI = 1 << 30;
    __syncthreads();
    if (L == m) atomicMin(&bestI, t);
    __syncthreads();
    int bi = bestI;
    float mx = g_cand[((size_t)(b * Sv + bi) * Nv + t) * 2 + 0];
    float my = g_cand[((size_t)(b * Sv + bi) * Nv + t) * 2 + 1];
    out[(b * Nv + t) * 2 + 0] = mx;
    out[(b * Nv + t) * 2 + 1] = my;
    out[2048 + b * Nv + t] =
        (mx >= 0.f && mx < (float)Wv && my >= 0.f && my < (float)Hv) ? 1.f : 0.f;
    float rad = radius[b];
    float sx = -1.f + (float)(t & 15) * (2.f / 15.f);
    float sy = -1.f + (float)(t >> 4) * (2.f / 15.f);
    out[3072 + (b * Sv + t) * 3 + 0] = tinit[b*3+0] + sx * rad;
    out[3072 + (b * Sv + t) * 3 + 1] = tinit[b*3+1] + sy * rad;
    out[3072 + (b * Sv + t) * 3 + 2] = tinit[b*3+2];
}

// ---------------- launch ----------------------------------------------------
extern "C" void kernel_launch(void* const* d_in, const int* in_sizes, int n_in,
                              void* d_out, int out_size) {
    const float* node_coords   = (const float*)d_in[0];
    const float* node_scores   = (const float*)d_in[1];
    const float* node_features = (const float*)d_in[2];
    const float* node_depths   = (const float*)d_in[3];
    const float* K_left        = (const float*)d_in[4];
    const float* R_left        = (const float*)d_in[5];
    const float* t_init        = (const float*)d_in[6];
    const float* sat_featmap   = (const float*)d_in[7];
    const float* K_sat         = (const float*)d_in[8];
    const float* R_sat         = (const float*)d_in[9];
    const float* t_sat         = (const float*)d_in[10];
    const float* radius        = (const float*)d_in[11];
    int off = (n_in >= 18) ? 0 : -1;
    const float* W_node      = (const float*)d_in[13 + off];
    const float* b_node      = (const float*)d_in[14 + off];
    const float* W_sat       = (const float*)d_in[15 + off];
    const float* b_sat       = (const float*)d_in[16 + off];
    const float* logit_scale = (const float*)d_in[17 + off];
    float* out = (float*)d_out;

    const int SMEM = 204800;
    cudaFuncSetAttribute(k_sfmma, cudaFuncAttributeMaxDynamicSharedMemorySize, SMEM);

    k_nf<<<128, 128>>>(node_features, W_node, b_node);
    k_worldR<<<4, 256>>>(node_coords, node_depths, K_left, R_left);
    k_sfmma<<<dim3(512, Bv), 256, SMEM>>>(sat_featmap, W_sat, b_sat);
    k_sample<<<dim3(Sv, Bv), 256>>>(K_sat, R_sat, t_sat, t_init, radius, node_scores);
    k_final<<<Bv, 256>>>(out, t_init, radius, logit_scale);
}

// round 9
// speedup vs baseline: 1.8680x; 1.3029x over previous
#include <cuda_runtime.h>
#include <cuda_bf16.h>
#include <math.h>
#include <stdint.h>

#define Bv   4
#define Nv   256
#define CIN  256
#define CH   128
#define Wv   256
#define Hv   256
#define HW   (Wv*Hv)
#define Sv   256

// ---------------- scratch ---------------------------------------------------
__device__ float g_nf[Bv*Nv*CH];
__device__ float g_pw[Bv*Nv*4];                 // (K_sat R_sat^T) @ worldR, padded
__device__ float g_sfn[(size_t)Bv*HW*CH];
__device__ float g_cand[Bv*Sv*Nv*2];
__device__ float g_logits[Bv*Sv];
__device__ __nv_bfloat16 g_Whl[2*128*256];      // W_sat bf16 hi ([0,32768)) + lo

// ---------------- helpers ---------------------------------------------------
__device__ __forceinline__ uint32_t s2u(const void* p){
    uint32_t a;
    asm("{ .reg .u64 t; cvta.to.shared.u64 t, %1; cvt.u32.u64 %0, t; }" : "=r"(a) : "l"(p));
    return a;
}
__device__ __forceinline__ uint32_t packbf(float lo_e, float hi_e){
    uint32_t r;   // lower 16 bits <- lo_e
    asm("cvt.rn.bf16x2.f32 %0, %1, %2;" : "=r"(r) : "f"(hi_e), "f"(lo_e));
    return r;
}
__device__ __forceinline__ float bfhi(float x){
    return __bfloat162float(__float2bfloat16_rn(x));
}
__device__ __forceinline__ void cvt_store8(char* hp, char* lp, float4 v){
    float h0=bfhi(v.x), h1=bfhi(v.y), h2=bfhi(v.z), h3=bfhi(v.w);
    uint2 H = make_uint2(packbf(h0,h1), packbf(h2,h3));
    uint2 L = make_uint2(packbf(v.x-h0, v.y-h1), packbf(v.z-h2, v.w-h3));
    *(uint2*)hp = H;
    *(uint2*)lp = L;
}
__device__ __forceinline__ void ldsm4(uint32_t* r, uint32_t addr){
    asm volatile("ldmatrix.sync.aligned.m8n8.x4.shared.b16 {%0,%1,%2,%3}, [%4];"
        : "=r"(r[0]), "=r"(r[1]), "=r"(r[2]), "=r"(r[3]) : "r"(addr));
}
__device__ __forceinline__ void ldsm4t(uint32_t* r, uint32_t addr){
    asm volatile("ldmatrix.sync.aligned.m8n8.x4.trans.shared.b16 {%0,%1,%2,%3}, [%4];"
        : "=r"(r[0]), "=r"(r[1]), "=r"(r[2]), "=r"(r[3]) : "r"(addr));
}
__device__ __forceinline__ void mma16816(float* d, const uint32_t* a, const uint32_t* b){
    asm volatile("mma.sync.aligned.m16n8k16.row.col.f32.bf16.bf16.f32 "
        "{%0,%1,%2,%3}, {%4,%5,%6,%7}, {%8,%9}, {%0,%1,%2,%3};"
        : "+f"(d[0]), "+f"(d[1]), "+f"(d[2]), "+f"(d[3])
        : "r"(a[0]), "r"(a[1]), "r"(a[2]), "r"(a[3]), "r"(b[0]), "r"(b[1]));
}
__device__ __forceinline__ void cpa16(uint32_t dst, const void* src){
    asm volatile("cp.async.ca.shared.global [%0], [%1], 16;" :: "r"(dst), "l"(src));
}
__device__ __forceinline__ void cpa_commit(){ asm volatile("cp.async.commit_group;"); }
__device__ __forceinline__ void cpa_wait0(){ asm volatile("cp.async.wait_group 0;" ::: "memory"); }

// ---------------- K0: W_sat -> bf16 hi/lo (once) ---------------------------
__global__ void k_wcvt(const float* __restrict__ Wsat) {
    int i = blockIdx.x * 256 + threadIdx.x;   // 0..32767
    float x = Wsat[i];
    __nv_bfloat16 h = __float2bfloat16_rn(x);
    g_Whl[i] = h;
    g_Whl[32768 + i] = __float2bfloat16_rn(x - __bfloat162float(h));
}

// ---------------- K1: nf = normalize(node_features @ W_node + b_node) ------
__global__ void k_nf(const float* __restrict__ nfeat,
                     const float* __restrict__ Wn,
                     const float* __restrict__ bn) {
    __shared__ float sf[8][CIN];
    __shared__ float red[8][128];
    __shared__ float sinv[8];
    int t = threadIdx.x;
    int cid = blockIdx.x;
    int b = cid >> 5;
    int n0 = (cid & 31) * 8;
    const float* src = nfeat + ((size_t)(b * Nv + n0)) * CIN;
    #pragma unroll
    for (int r = 0; r < 16; r++) {
        int idx = r * 128 + t;
        sf[idx >> 8][idx & 255] = src[idx];
    }
    __syncthreads();
    float acc[8];
    float bj = bn[t];
    #pragma unroll
    for (int i = 0; i < 8; i++) acc[i] = bj;
    for (int k = 0; k < CIN; k++) {
        float w = Wn[k * CH + t];
        #pragma unroll
        for (int i = 0; i < 8; i++) acc[i] += sf[i][k] * w;
    }
    #pragma unroll
    for (int i = 0; i < 8; i++) red[i][t] = acc[i] * acc[i];
    __syncthreads();
    if (t < 8) {
        float s = 0.f;
        for (int j = 0; j < 128; j++) s += red[t][j];
        sinv[t] = 1.0f / fmaxf(sqrtf(s), 1e-12f);
    }
    __syncthreads();
    #pragma unroll
    for (int i = 0; i < 8; i++)
        g_nf[(size_t)(b * Nv + n0 + i) * CH + t] = acc[i] * sinv[i];
}

// ---------------- K2: per-node projected ray endpoints ---------------------
__global__ void k_pw(const float* __restrict__ coords,
                     const float* __restrict__ depths,
                     const float* __restrict__ Kl,
                     const float* __restrict__ Rl,
                     const float* __restrict__ Ks,
                     const float* __restrict__ Rs) {
    int idx = blockIdx.x * blockDim.x + threadIdx.x;
    if (idx >= Bv * Nv) return;
    int b = idx / Nv;
    const float* K = Kl + b * 9;
    float a00=K[0],a01=K[1],a02=K[2],a10=K[3],a11=K[4],a12=K[5],a20=K[6],a21=K[7],a22=K[8];
    float c00 = a11*a22 - a12*a21, c01 = a02*a21 - a01*a22, c02 = a01*a12 - a02*a11;
    float c10 = a12*a20 - a10*a22, c11 = a00*a22 - a02*a20, c12 = a02*a10 - a00*a12;
    float c20 = a10*a21 - a11*a20, c21 = a01*a20 - a00*a21, c22 = a00*a11 - a01*a10;
    float det = a00*c00 + a01*c10 + a02*c20;
    float id = 1.0f / det;
    float u = coords[idx*2+0], v = coords[idx*2+1];
    float d = depths[idx];
    float cx = (c00*u + c01*v + c02) * id * d;
    float cy = (c10*u + c11*v + c12) * id * d;
    float cz = (c20*u + c21*v + c22) * id * d;
    const float* R = Rl + b * 9;
    float wx = R[0]*cx + R[1]*cy + R[2]*cz;
    float wy = R[3]*cx + R[4]*cy + R[5]*cz;
    float wz = R[6]*cx + R[7]*cy + R[8]*cz;
    const float* Km = Ks + b * 9;
    const float* Rm = Rs + b * 9;
    float P[9];
    #pragma unroll
    for (int i = 0; i < 3; i++)
        #pragma unroll
        for (int j = 0; j < 3; j++)
            P[i*3+j] = Km[i*3+0]*Rm[j*3+0] + Km[i*3+1]*Rm[j*3+1] + Km[i*3+2]*Rm[j*3+2];
    g_pw[idx*4+0] = P[0]*wx + P[1]*wy + P[2]*wz;
    g_pw[idx*4+1] = P[3]*wx + P[4]*wy + P[5]*wz;
    g_pw[idx*4+2] = P[6]*wx + P[7]*wy + P[8]*wz;
    g_pw[idx*4+3] = 0.f;
}

// ---------------- K3: sf_norm via mma.sync bf16-split, 2 CTA/SM ------------
// D[o=128][px=128] = sum_c W[o][c]*feat[c][px]; K=256 as 8 chunks of 32.
// A = pre-converted bf16 W (cp.async), B = feat fp32 cp.async stage -> bf16.
// A_PITCH must be a multiple of 16 (cp.async dst alignment): 80.
#define A_PITCH 80
#define AHALF   10240
#define ABUF    20480
#define B_PITCH 272
#define BHALF   8704
#define BBUF    17408
#define OFF_A   0
#define OFF_B   40960
#define OFF_S   75776
#define SMEM_K3 92160

__global__ __launch_bounds__(256, 2) void k_sfmma(const float* __restrict__ feat,
                                                  const float* __restrict__ bsat) {
    extern __shared__ char dsm[];
    __shared__ float s_inv[128];
    uint32_t sb = s2u(dsm);

    int t = threadIdx.x, wid = t >> 5, lane = t & 31;
    int warp_m = wid & 3, warp_n = wid >> 2;
    int b = blockIdx.y, p0 = blockIdx.x * 128;
    const float* fb = feat + (size_t)b * CIN * HW + p0;

    // issue A chunk (bf16 hi+lo from global) via cp.async
    auto issueA = [&](int chunk, int buf){
        #pragma unroll
        for (int j = 0; j < 4; j++) {
            int u = j * 256 + t;
            int half = u >> 9, w = u & 511;
            int o = w >> 2, seg = w & 3;
            uint32_t dst = sb + OFF_A + buf * ABUF + half * AHALF + o * A_PITCH + seg * 16;
            const char* src = (const char*)g_Whl + half * 65536 + o * 512 + chunk * 64 + seg * 16;
            cpa16(dst, src);
        }
    };
    // issue feat chunk fp32 -> stage (own-unit mapping)
    auto issueB = [&](int chunk){
        #pragma unroll
        for (int j = 0; j < 4; j++) {
            int idx = j * 256 + t;
            int c = idx >> 5, pxg = idx & 31;
            cpa16(sb + OFF_S + idx * 16, fb + (size_t)(chunk * 32 + c) * HW + pxg * 4);
        }
    };
    // convert own stage units -> bf16 hi/lo buffers
    auto convB = [&](int buf){
        #pragma unroll
        for (int j = 0; j < 4; j++) {
            int idx = j * 256 + t;
            int c = idx >> 5, pxg = idx & 31;
            float4 v = *(const float4*)(dsm + OFF_S + idx * 16);
            cvt_store8(dsm + OFF_B + buf * BBUF + c * B_PITCH + pxg * 8,
                       dsm + OFF_B + buf * BBUF + BHALF + c * B_PITCH + pxg * 8, v);
        }
    };

    issueA(0, 0);
    issueB(0);
    cpa_commit();
    cpa_wait0();
    convB(0);
    __syncthreads();

    uint32_t lrow = lane & 15;
    uint32_t lsel = (lane >> 4) & 1;
    uint32_t aRow = (uint32_t)(warp_m * 32 + lrow) * A_PITCH + lsel * 16;
    uint32_t bCol = (uint32_t)(warp_n * 64 + lsel * 8) * 2;

    float acc[2][8][4];
    #pragma unroll
    for (int i = 0; i < 2; i++)
        #pragma unroll
        for (int j = 0; j < 8; j++)
            #pragma unroll
            for (int r = 0; r < 4; r++) acc[i][j][r] = 0.f;

    for (int c = 0; c < 8; c++) {
        if (c < 7) {
            issueA(c + 1, (c + 1) & 1);
            issueB(c + 1);
            cpa_commit();
        }
        uint32_t abase = sb + OFF_A + (uint32_t)(c & 1) * ABUF;
        uint32_t bbase = sb + OFF_B + (uint32_t)(c & 1) * BBUF;
        #pragma unroll
        for (int ks = 0; ks < 2; ks++) {
            uint32_t ao = aRow + (uint32_t)ks * 32;
            uint32_t ah[2][4], al[2][4];
            ldsm4(ah[0], abase + ao);
            ldsm4(ah[1], abase + 16 * A_PITCH + ao);
            ldsm4(al[0], abase + AHALF + ao);
            ldsm4(al[1], abase + AHALF + 16 * A_PITCH + ao);
            #pragma unroll
            for (int nf2 = 0; nf2 < 4; nf2++) {
                uint32_t bo = (uint32_t)(ks * 16 + lrow) * B_PITCH + bCol + (uint32_t)nf2 * 32;
                uint32_t bh[4], bl[4];
                ldsm4t(bh, bbase + bo);
                ldsm4t(bl, bbase + BHALF + bo);
                #pragma unroll
                for (int fm = 0; fm < 2; fm++) {
                    mma16816(acc[fm][2*nf2],     ah[fm], bh + 0);
                    mma16816(acc[fm][2*nf2],     ah[fm], bl + 0);
                    mma16816(acc[fm][2*nf2],     al[fm], bh + 0);
                    mma16816(acc[fm][2*nf2 + 1], ah[fm], bh + 2);
                    mma16816(acc[fm][2*nf2 + 1], ah[fm], bl + 2);
                    mma16816(acc[fm][2*nf2 + 1], al[fm], bh + 2);
                }
            }
        }
        if (c < 7) {
            cpa_wait0();
            convB((c + 1) & 1);
        }
        __syncthreads();
    }

    // ---- epilogue: stage [px][o] (+bias), per-px L2 norm, coalesced store --
    float* stg = (float*)dsm;          // 128 px x 132 floats (aliases A/B bufs)
    float bias0[2], bias1[2];
    #pragma unroll
    for (int fm = 0; fm < 2; fm++) {
        int m = warp_m * 32 + fm * 16 + (lane >> 2);
        bias0[fm] = bsat[m];
        bias1[fm] = bsat[m + 8];
    }
    #pragma unroll
    for (int fm = 0; fm < 2; fm++) {
        int m0 = warp_m * 32 + fm * 16 + (lane >> 2);
        #pragma unroll
        for (int fn = 0; fn < 8; fn++) {
            int n0 = warp_n * 64 + fn * 8 + (lane & 3) * 2;
            stg[n0 * 132 + m0]           = acc[fm][fn][0] + bias0[fm];
            stg[(n0 + 1) * 132 + m0]     = acc[fm][fn][1] + bias0[fm];
            stg[n0 * 132 + m0 + 8]       = acc[fm][fn][2] + bias1[fm];
            stg[(n0 + 1) * 132 + m0 + 8] = acc[fm][fn][3] + bias1[fm];
        }
    }
    __syncthreads();
    if (t < 128) {
        float ss = 0.f;
        #pragma unroll
        for (int o4 = 0; o4 < 32; o4++) {
            float4 v = *(const float4*)&stg[t * 132 + o4 * 4];
            ss += v.x*v.x + v.y*v.y + v.z*v.z + v.w*v.w;
        }
        s_inv[t] = 1.0f / fmaxf(sqrtf(ss), 1e-12f);
    }
    __syncthreads();
    float* outp = g_sfn + ((size_t)b * HW + p0) * CH;
    #pragma unroll
    for (int it = 0; it < 16; it++) {
        int idx = it * 256 + t;
        int px = idx >> 5, cg = idx & 31;
        float4 v = *(const float4*)&stg[px * 132 + cg * 4];
        float inv = s_inv[px];
        v.x *= inv; v.y *= inv; v.z *= inv; v.w *= inv;
        *(float4*)&outp[(size_t)px * CH + cg * 4] = v;
    }
}

// ---------------- K4: per-(b,s) projection + bilinear dot + logits ---------
__global__ __launch_bounds__(256) void k_sample(const float* __restrict__ Ksat,
                                                const float* __restrict__ Rsat,
                                                const float* __restrict__ tsat,
                                                const float* __restrict__ tinit,
                                                const float* __restrict__ radius,
                                                const float* __restrict__ scores) {
    int s = blockIdx.x, b = blockIdx.y;
    int t = threadIdx.x;
    int w = t >> 5, lane = t & 31;
    __shared__ float warpsum[8];
    float rx, ry, rz;
    {
        const float* Km = Ksat + b * 9;
        const float* Rm = Rsat + b * 9;
        float rad = radius[b];
        float stepx = -1.f + (float)(s & 15) * (2.f / 15.f);
        float stepy = -1.f + (float)(s >> 4) * (2.f / 15.f);
        float dx = tinit[b*3+0] + stepx * rad - tsat[b*3+0];
        float dy = tinit[b*3+1] + stepy * rad - tsat[b*3+1];
        float dz = tinit[b*3+2] - tsat[b*3+2];
        float P[9];
        #pragma unroll
        for (int i = 0; i < 3; i++)
            #pragma unroll
            for (int j = 0; j < 3; j++)
                P[i*3+j] = Km[i*3+0]*Rm[j*3+0] + Km[i*3+1]*Rm[j*3+1] + Km[i*3+2]*Rm[j*3+2];
        rx = P[0]*dx + P[1]*dy + P[2]*dz;
        ry = P[3]*dx + P[4]*dy + P[5]*dz;
        rz = P[6]*dx + P[7]*dy + P[8]*dz;
    }

    float lacc = 0.f;
    for (int n = w; n < Nv; n += 8) {
        float4 pw = *(const float4*)(g_pw + (b * Nv + n) * 4);
        float ww = pw.z + rz;
        float candx = (pw.x + rx) / ww;
        float candy = (pw.y + ry) / ww;
        if (lane == 0) {
            g_cand[((size_t)(b*Sv + s) * Nv + n) * 2 + 0] = candx;
            g_cand[((size_t)(b*Sv + s) * Nv + n) * 2 + 1] = candy;
        }
        float ncx = candx / 255.0f * 2.0f - 1.0f;
        float ncy = candy / 255.0f * 2.0f - 1.0f;
        float px = ((ncx + 1.f) * (float)Wv - 1.f) * 0.5f;
        float py = ((ncy + 1.f) * (float)Hv - 1.f) * 0.5f;
        float x0f = floorf(px), y0f = floorf(py);
        float wx1 = px - x0f, wx0v = 1.f - wx1;
        float wy1 = py - y0f, wy0v = 1.f - wy1;
        float4 nfv = *(const float4*)(g_nf + (size_t)(b * Nv + n) * CH + lane * 4);
        float cw[4] = {wy0v*wx0v, wy0v*wx1, wy1*wx0v, wy1*wx1};
        float xs[4] = {x0f, x0f + 1.f, x0f, x0f + 1.f};
        float ys[4] = {y0f, y0f, y0f + 1.f, y0f + 1.f};
        float nodeacc = 0.f;
        #pragma unroll
        for (int c = 0; c < 4; c++) {
            float xf = xs[c], yf = ys[c];
            bool valid = (xf >= 0.f) && (xf <= 255.f) && (yf >= 0.f) && (yf <= 255.f);
            if (valid) {
                int xi = (int)xf, yi = (int)yf;
                float4 sv = *(const float4*)(g_sfn +
                    ((size_t)b * HW + yi * Wv + xi) * CH + lane * 4);
                float d = nfv.x*sv.x + nfv.y*sv.y + nfv.z*sv.z + nfv.w*sv.w;
                nodeacc += cw[c] * d;
            }
        }
        lacc += scores[b * Nv + n] * nodeacc;
    }
    #pragma unroll
    for (int o = 16; o > 0; o >>= 1) lacc += __shfl_down_sync(0xffffffffu, lacc, o);
    if (lane == 0) warpsum[w] = lacc;
    __syncthreads();
    if (t == 0) {
        float s8 = 0.f;
        #pragma unroll
        for (int i = 0; i < 8; i++) s8 += warpsum[i];
        g_logits[b * Sv + s] = s8;
    }
}

// ---------------- K5: softmax, argmax, outputs -----------------------------
__global__ void k_final(float* __restrict__ out,
                        const float* __restrict__ tinit,
                        const float* __restrict__ radius,
                        const float* __restrict__ lscale) {
    int b = blockIdx.x;
    int t = threadIdx.x;   // 256
    __shared__ float sred[256];
    __shared__ int bestI;
    float escale = expf(lscale[0]);
    float L = g_logits[b * Sv + t] * escale;
    sred[t] = L; __syncthreads();
    for (int o = 128; o > 0; o >>= 1) {
        if (t < o) sred[t] = fmaxf(sred[t], sred[t + o]);
        __syncthreads();
    }
    float m = sred[0];
    __syncthreads();
    float e = expf(L - m);
    sred[t] = e; __syncthreads();
    for (int o = 128; o > 0; o >>= 1) {
        if (t < o) sred[t] += sred[t + o];
        __syncthreads();
    }
    float Z = sred[0];
    out[6144 + b * Sv + t] = e / Z;
    if (t == 0) bestI = 1 << 30;
    __syncthreads();
    if (L == m) atomicMin(&bestI, t);
    __syncthreads();
    int bi = bestI;
    float mx = g_cand[((size_t)(b * Sv + bi) * Nv + t) * 2 + 0];
    float my = g_cand[((size_t)(b * Sv + bi) * Nv + t) * 2 + 1];
    out[(b * Nv + t) * 2 + 0] = mx;
    out[(b * Nv + t) * 2 + 1] = my;
    out[2048 + b * Nv + t] =
        (mx >= 0.f && mx < (float)Wv && my >= 0.f && my < (float)Hv) ? 1.f : 0.f;
    float rad = radius[b];
    float sx = -1.f + (float)(t & 15) * (2.f / 15.f);
    float sy = -1.f + (float)(t >> 4) * (2.f / 15.f);
    out[3072 + (b * Sv + t) * 3 + 0] = tinit[b*3+0] + sx * rad;
    out[3072 + (b * Sv + t) * 3 + 1] = tinit[b*3+1] + sy * rad;
    out[3072 + (b * Sv + t) * 3 + 2] = tinit[b*3+2];
}

// ---------------- launch ----------------------------------------------------
extern "C" void kernel_launch(void* const* d_in, const int* in_sizes, int n_in,
                              void* d_out, int out_size) {
    const float* node_coords   = (const float*)d_in[0];
    const float* node_scores   = (const float*)d_in[1];
    const float* node_features = (const float*)d_in[2];
    const float* node_depths   = (const float*)d_in[3];
    const float* K_left        = (const float*)d_in[4];
    const float* R_left        = (const float*)d_in[5];
    const float* t_init        = (const float*)d_in[6];
    const float* sat_featmap   = (const float*)d_in[7];
    const float* K_sat         = (const float*)d_in[8];
    const float* R_sat         = (const float*)d_in[9];
    const float* t_sat         = (const float*)d_in[10];
    const float* radius        = (const float*)d_in[11];
    int off = (n_in >= 18) ? 0 : -1;
    const float* W_node      = (const float*)d_in[13 + off];
    const float* b_node      = (const float*)d_in[14 + off];
    const float* W_sat       = (const float*)d_in[15 + off];
    const float* b_sat       = (const float*)d_in[16 + off];
    const float* logit_scale = (const float*)d_in[17 + off];
    float* out = (float*)d_out;

    cudaFuncSetAttribute(k_sfmma, cudaFuncAttributeMaxDynamicSharedMemorySize, SMEM_K3);

    k_wcvt<<<128, 256>>>(W_sat);
    k_nf<<<128, 128>>>(node_features, W_node, b_node);
    k_pw<<<4, 256>>>(node_coords, node_depths, K_left, R_left, K_sat, R_sat);
    k_sfmma<<<dim3(512, Bv), 256, SMEM_K3>>>(sat_featmap, b_sat);
    k_sample<<<dim3(Sv, Bv), 256>>>(K_sat, R_sat, t_sat, t_init, radius, node_scores);
    k_final<<<Bv, 256>>>(out, t_init, radius, logit_scale);
}

// round 10
// speedup vs baseline: 2.4028x; 1.2863x over previous
#include <cuda_runtime.h>
#include <cuda_bf16.h>
#include <cuda_fp16.h>
#include <math.h>
#include <stdint.h>

#define Bv   4
#define Nv   256
#define CIN  256
#define CH   128
#define Wv   256
#define Hv   256
#define HW   (Wv*Hv)
#define Sv   256

// ---------------- scratch ---------------------------------------------------
__device__ float g_nf[Bv*Nv*CH];
__device__ float g_pw[Bv*Nv*4];                 // (K_sat R_sat^T) @ worldR, padded
__device__ float g_sfn[(size_t)Bv*HW*CH];
__device__ float g_cand[Bv*Sv*Nv*2];
__device__ float g_logits[Bv*Sv];
__device__ __half g_Whl[2*128*256];             // 16*W_sat fp16 hi ([0,32768)) + lo

// ---------------- helpers ---------------------------------------------------
__device__ __forceinline__ uint32_t s2u(const void* p){
    uint32_t a;
    asm("{ .reg .u64 t; cvta.to.shared.u64 t, %1; cvt.u32.u64 %0, t; }" : "=r"(a) : "l"(p));
    return a;
}
__device__ __forceinline__ uint32_t packh2(float lo_e, float hi_e){
    uint32_t r;   // lower 16 bits <- lo_e (first in memory)
    asm("cvt.rn.f16x2.f32 %0, %1, %2;" : "=r"(r) : "f"(hi_e), "f"(lo_e));
    return r;
}
__device__ __forceinline__ void ldsm4(uint32_t* r, uint32_t addr){
    asm volatile("ldmatrix.sync.aligned.m8n8.x4.shared.b16 {%0,%1,%2,%3}, [%4];"
        : "=r"(r[0]), "=r"(r[1]), "=r"(r[2]), "=r"(r[3]) : "r"(addr));
}
__device__ __forceinline__ void ldsm4t(uint32_t* r, uint32_t addr){
    asm volatile("ldmatrix.sync.aligned.m8n8.x4.trans.shared.b16 {%0,%1,%2,%3}, [%4];"
        : "=r"(r[0]), "=r"(r[1]), "=r"(r[2]), "=r"(r[3]) : "r"(addr));
}
__device__ __forceinline__ void mma16816(float* d, const uint32_t* a, const uint32_t* b){
    asm volatile("mma.sync.aligned.m16n8k16.row.col.f32.f16.f16.f32 "
        "{%0,%1,%2,%3}, {%4,%5,%6,%7}, {%8,%9}, {%0,%1,%2,%3};"
        : "+f"(d[0]), "+f"(d[1]), "+f"(d[2]), "+f"(d[3])
        : "r"(a[0]), "r"(a[1]), "r"(a[2]), "r"(a[3]), "r"(b[0]), "r"(b[1]));
}
__device__ __forceinline__ void cpa16(uint32_t dst, const void* src){
    asm volatile("cp.async.ca.shared.global [%0], [%1], 16;" :: "r"(dst), "l"(src));
}
__device__ __forceinline__ void cpa_commit(){ asm volatile("cp.async.commit_group;"); }
__device__ __forceinline__ void cpa_wait0(){ asm volatile("cp.async.wait_group 0;" ::: "memory"); }

// ---------------- K0: 16*W_sat -> fp16 hi/lo (once) ------------------------
__global__ void k_wcvt(const float* __restrict__ Wsat) {
    int i = blockIdx.x * 256 + threadIdx.x;   // 0..32767
    float x = Wsat[i] * 16.0f;
    __half h = __float2half_rn(x);
    g_Whl[i] = h;
    g_Whl[32768 + i] = __float2half_rn(x - __half2float(h));
}

// ---------------- K1: nf = normalize(node_features @ W_node + b_node) ------
__global__ void k_nf(const float* __restrict__ nfeat,
                     const float* __restrict__ Wn,
                     const float* __restrict__ bn) {
    __shared__ float sf[8][CIN];
    __shared__ float red[8][128];
    __shared__ float sinv[8];
    int t = threadIdx.x;
    int cid = blockIdx.x;
    int b = cid >> 5;
    int n0 = (cid & 31) * 8;
    const float* src = nfeat + ((size_t)(b * Nv + n0)) * CIN;
    #pragma unroll
    for (int r = 0; r < 16; r++) {
        int idx = r * 128 + t;
        sf[idx >> 8][idx & 255] = src[idx];
    }
    __syncthreads();
    float acc[8];
    float bj = bn[t];
    #pragma unroll
    for (int i = 0; i < 8; i++) acc[i] = bj;
    for (int k = 0; k < CIN; k++) {
        float w = Wn[k * CH + t];
        #pragma unroll
        for (int i = 0; i < 8; i++) acc[i] += sf[i][k] * w;
    }
    #pragma unroll
    for (int i = 0; i < 8; i++) red[i][t] = acc[i] * acc[i];
    __syncthreads();
    if (t < 8) {
        float s = 0.f;
        for (int j = 0; j < 128; j++) s += red[t][j];
        sinv[t] = 1.0f / fmaxf(sqrtf(s), 1e-12f);
    }
    __syncthreads();
    #pragma unroll
    for (int i = 0; i < 8; i++)
        g_nf[(size_t)(b * Nv + n0 + i) * CH + t] = acc[i] * sinv[i];
}

// ---------------- K2: per-node projected ray endpoints ---------------------
__global__ void k_pw(const float* __restrict__ coords,
                     const float* __restrict__ depths,
                     const float* __restrict__ Kl,
                     const float* __restrict__ Rl,
                     const float* __restrict__ Ks,
                     const float* __restrict__ Rs) {
    int idx = blockIdx.x * blockDim.x + threadIdx.x;
    if (idx >= Bv * Nv) return;
    int b = idx / Nv;
    const float* K = Kl + b * 9;
    float a00=K[0],a01=K[1],a02=K[2],a10=K[3],a11=K[4],a12=K[5],a20=K[6],a21=K[7],a22=K[8];
    float c00 = a11*a22 - a12*a21, c01 = a02*a21 - a01*a22, c02 = a01*a12 - a02*a11;
    float c10 = a12*a20 - a10*a22, c11 = a00*a22 - a02*a20, c12 = a02*a10 - a00*a12;
    float c20 = a10*a21 - a11*a20, c21 = a01*a20 - a00*a21, c22 = a00*a11 - a01*a10;
    float det = a00*c00 + a01*c10 + a02*c20;
    float id = 1.0f / det;
    float u = coords[idx*2+0], v = coords[idx*2+1];
    float d = depths[idx];
    float cx = (c00*u + c01*v + c02) * id * d;
    float cy = (c10*u + c11*v + c12) * id * d;
    float cz = (c20*u + c21*v + c22) * id * d;
    const float* R = Rl + b * 9;
    float wx = R[0]*cx + R[1]*cy + R[2]*cz;
    float wy = R[3]*cx + R[4]*cy + R[5]*cz;
    float wz = R[6]*cx + R[7]*cy + R[8]*cz;
    const float* Km = Ks + b * 9;
    const float* Rm = Rs + b * 9;
    float P[9];
    #pragma unroll
    for (int i = 0; i < 3; i++)
        #pragma unroll
        for (int j = 0; j < 3; j++)
            P[i*3+j] = Km[i*3+0]*Rm[j*3+0] + Km[i*3+1]*Rm[j*3+1] + Km[i*3+2]*Rm[j*3+2];
    g_pw[idx*4+0] = P[0]*wx + P[1]*wy + P[2]*wz;
    g_pw[idx*4+1] = P[3]*wx + P[4]*wy + P[5]*wz;
    g_pw[idx*4+2] = P[6]*wx + P[7]*wy + P[8]*wz;
    g_pw[idx*4+3] = 0.f;
}

// ---------------- K3: sf_norm via mma.sync fp16 2-term, 2 CTA/SM -----------
// D[o=128][px=128] = (1/16) sum_c (16W)[o][c]*feat[c][px]; K=256 as 8 chunks
// of 32. A = pre-scaled fp16 W hi+lo (cp.async), B = feat single fp16
// (LDG regs -> convert). Terms: Ah*B + Al*B.
#define A_PITCH 80
#define AHALF   10240
#define ABUF    20480
#define B_PITCH 272
#define BBUF    8704
#define OFF_A   0
#define OFF_B   40960
#define SMEM_K3 67584

__global__ __launch_bounds__(256, 2) void k_sfmma(const float* __restrict__ feat,
                                                  const float* __restrict__ bsat) {
    extern __shared__ char dsm[];
    __shared__ float s_inv[128];
    uint32_t sb = s2u(dsm);

    int t = threadIdx.x, wid = t >> 5, lane = t & 31;
    int warp_m = wid & 3, warp_n = wid >> 2;
    int b = blockIdx.y, p0 = blockIdx.x * 128;
    const float* fb = feat + (size_t)b * CIN * HW + p0;

    // issue A chunk (fp16 hi+lo from global) via cp.async
    auto issueA = [&](int chunk, int buf){
        #pragma unroll
        for (int j = 0; j < 4; j++) {
            int u = j * 256 + t;
            int half = u >> 9, w = u & 511;
            int o = w >> 2, seg = w & 3;
            uint32_t dst = sb + OFF_A + buf * ABUF + half * AHALF + o * A_PITCH + seg * 16;
            const char* src = (const char*)g_Whl + half * 65536 + o * 512 + chunk * 64 + seg * 16;
            cpa16(dst, src);
        }
    };
    // load feat chunk to regs
    auto loadB = [&](int chunk, float4* pre){
        #pragma unroll
        for (int j = 0; j < 4; j++) {
            int idx = j * 256 + t;
            int c = idx >> 5, pxg = idx & 31;
            pre[j] = *(const float4*)(fb + (size_t)(chunk * 32 + c) * HW + pxg * 4);
        }
    };
    // convert regs -> fp16 B buffer
    auto convB = [&](int buf, const float4* pre){
        #pragma unroll
        for (int j = 0; j < 4; j++) {
            int idx = j * 256 + t;
            int c = idx >> 5, pxg = idx & 31;
            float4 v = pre[j];
            uint2 u = make_uint2(packh2(v.x, v.y), packh2(v.z, v.w));
            *(uint2*)(dsm + OFF_B + buf * BBUF + c * B_PITCH + pxg * 8) = u;
        }
    };

    float4 pre[4];
    loadB(0, pre);
    issueA(0, 0);
    cpa_commit();
    cpa_wait0();
    convB(0, pre);
    __syncthreads();

    uint32_t lrow = lane & 15;
    uint32_t lsel = (lane >> 4) & 1;
    uint32_t aRow = (uint32_t)(warp_m * 32 + lrow) * A_PITCH + lsel * 16;
    uint32_t bCol = (uint32_t)(warp_n * 64 + lsel * 8) * 2;

    float acc[2][8][4];
    #pragma unroll
    for (int i = 0; i < 2; i++)
        #pragma unroll
        for (int j = 0; j < 8; j++)
            #pragma unroll
            for (int r = 0; r < 4; r++) acc[i][j][r] = 0.f;

    for (int c = 0; c < 8; c++) {
        if (c < 7) {
            loadB(c + 1, pre);
            issueA(c + 1, (c + 1) & 1);
            cpa_commit();
        }
        uint32_t abase = sb + OFF_A + (uint32_t)(c & 1) * ABUF;
        uint32_t bbase = sb + OFF_B + (uint32_t)(c & 1) * BBUF;
        #pragma unroll
        for (int ks = 0; ks < 2; ks++) {
            uint32_t ao = aRow + (uint32_t)ks * 32;
            uint32_t ah[2][4], al[2][4];
            ldsm4(ah[0], abase + ao);
            ldsm4(ah[1], abase + 16 * A_PITCH + ao);
            ldsm4(al[0], abase + AHALF + ao);
            ldsm4(al[1], abase + AHALF + 16 * A_PITCH + ao);
            #pragma unroll
            for (int nf2 = 0; nf2 < 4; nf2++) {
                uint32_t bo = (uint32_t)(ks * 16 + lrow) * B_PITCH + bCol + (uint32_t)nf2 * 32;
                uint32_t bb[4];
                ldsm4t(bb, bbase + bo);
                #pragma unroll
                for (int fm = 0; fm < 2; fm++) {
                    mma16816(acc[fm][2*nf2],     ah[fm], bb + 0);
                    mma16816(acc[fm][2*nf2],     al[fm], bb + 0);
                    mma16816(acc[fm][2*nf2 + 1], ah[fm], bb + 2);
                    mma16816(acc[fm][2*nf2 + 1], al[fm], bb + 2);
                }
            }
        }
        if (c < 7) {
            cpa_wait0();
            convB((c + 1) & 1, pre);
        }
        __syncthreads();
    }

    // ---- epilogue: stage [px][o] (scale+bias), per-px L2 norm, store ------
    float* stg = (float*)dsm;          // 128 px x 132 floats (aliases A/B bufs)
    const float SC = 0.0625f;
    float bias0[2], bias1[2];
    #pragma unroll
    for (int fm = 0; fm < 2; fm++) {
        int m = warp_m * 32 + fm * 16 + (lane >> 2);
        bias0[fm] = bsat[m];
        bias1[fm] = bsat[m + 8];
    }
    #pragma unroll
    for (int fm = 0; fm < 2; fm++) {
        int m0 = warp_m * 32 + fm * 16 + (lane >> 2);
        #pragma unroll
        for (int fn = 0; fn < 8; fn++) {
            int n0 = warp_n * 64 + fn * 8 + (lane & 3) * 2;
            stg[n0 * 132 + m0]           = acc[fm][fn][0] * SC + bias0[fm];
            stg[(n0 + 1) * 132 + m0]     = acc[fm][fn][1] * SC + bias0[fm];
            stg[n0 * 132 + m0 + 8]       = acc[fm][fn][2] * SC + bias1[fm];
            stg[(n0 + 1) * 132 + m0 + 8] = acc[fm][fn][3] * SC + bias1[fm];
        }
    }
    __syncthreads();
    if (t < 128) {
        float ss = 0.f;
        #pragma unroll
        for (int o4 = 0; o4 < 32; o4++) {
            float4 v = *(const float4*)&stg[t * 132 + o4 * 4];
            ss += v.x*v.x + v.y*v.y + v.z*v.z + v.w*v.w;
        }
        s_inv[t] = 1.0f / fmaxf(sqrtf(ss), 1e-12f);
    }
    __syncthreads();
    float* outp = g_sfn + ((size_t)b * HW + p0) * CH;
    #pragma unroll
    for (int it = 0; it < 16; it++) {
        int idx = it * 256 + t;
        int px = idx >> 5, cg = idx & 31;
        float4 v = *(const float4*)&stg[px * 132 + cg * 4];
        float inv = s_inv[px];
        v.x *= inv; v.y *= inv; v.z *= inv; v.w *= inv;
        *(float4*)&outp[(size_t)px * CH + cg * 4] = v;
    }
}

// ---------------- K4: per-(b,s) projection + bilinear dot + logits ---------
__global__ __launch_bounds__(256) void k_sample(const float* __restrict__ Ksat,
                                                const float* __restrict__ Rsat,
                                                const float* __restrict__ tsat,
                                                const float* __restrict__ tinit,
                                                const float* __restrict__ radius,
                                                const float* __restrict__ scores) {
    int s = blockIdx.x, b = blockIdx.y;
    int t = threadIdx.x;
    int w = t >> 5, lane = t & 31;
    __shared__ float warpsum[8];
    float rx, ry, rz;
    {
        const float* Km = Ksat + b * 9;
        const float* Rm = Rsat + b * 9;
        float rad = radius[b];
        float stepx = -1.f + (float)(s & 15) * (2.f / 15.f);
        float stepy = -1.f + (float)(s >> 4) * (2.f / 15.f);
        float dx = tinit[b*3+0] + stepx * rad - tsat[b*3+0];
        float dy = tinit[b*3+1] + stepy * rad - tsat[b*3+1];
        float dz = tinit[b*3+2] - tsat[b*3+2];
        float P[9];
        #pragma unroll
        for (int i = 0; i < 3; i++)
            #pragma unroll
            for (int j = 0; j < 3; j++)
                P[i*3+j] = Km[i*3+0]*Rm[j*3+0] + Km[i*3+1]*Rm[j*3+1] + Km[i*3+2]*Rm[j*3+2];
        rx = P[0]*dx + P[1]*dy + P[2]*dz;
        ry = P[3]*dx + P[4]*dy + P[5]*dz;
        rz = P[6]*dx + P[7]*dy + P[8]*dz;
    }

    const float* sfb = g_sfn + (size_t)b * HW * CH;
    float lacc = 0.f;
    #pragma unroll 1
    for (int n = w; n < Nv; n += 16) {
        int n2 = n + 8;
        float4 pwA = *(const float4*)(g_pw + (b * Nv + n) * 4);
        float4 pwB = *(const float4*)(g_pw + (b * Nv + n2) * 4);
        float4 nfA = *(const float4*)(g_nf + (size_t)(b * Nv + n) * CH + lane * 4);
        float4 nfB = *(const float4*)(g_nf + (size_t)(b * Nv + n2) * CH + lane * 4);
        float wwA = pwA.z + rz, wwB = pwB.z + rz;
        float cxA = (pwA.x + rx) / wwA, cyA = (pwA.y + ry) / wwA;
        float cxB = (pwB.x + rx) / wwB, cyB = (pwB.y + ry) / wwB;
        if (lane == 0) {
            float2* cd = (float2*)(g_cand + ((size_t)(b*Sv + s) * Nv) * 2);
            cd[n]  = make_float2(cxA, cyA);
            cd[n2] = make_float2(cxB, cyB);
        }
        // pixel coords
        float pxA = ((cxA / 255.0f * 2.0f) * (float)Wv - 1.f) * 0.5f;
        float pyA = ((cyA / 255.0f * 2.0f) * (float)Hv - 1.f) * 0.5f;
        float pxB = ((cxB / 255.0f * 2.0f) * (float)Wv - 1.f) * 0.5f;
        float pyB = ((cyB / 255.0f * 2.0f) * (float)Hv - 1.f) * 0.5f;
        float x0A = floorf(pxA), y0A = floorf(pyA);
        float x0B = floorf(pxB), y0B = floorf(pyB);
        float fxA = pxA - x0A, fyA = pyA - y0A;
        float fxB = pxB - x0B, fyB = pyB - y0B;
        float cwA[4] = {(1.f-fyA)*(1.f-fxA), (1.f-fyA)*fxA, fyA*(1.f-fxA), fyA*fxA};
        float cwB[4] = {(1.f-fyB)*(1.f-fxB), (1.f-fyB)*fxB, fyB*(1.f-fxB), fyB*fxB};
        float accA = 0.f, accB = 0.f;
        #pragma unroll
        for (int cc = 0; cc < 4; cc++) {
            float xfA = x0A + (float)(cc & 1), yfA = y0A + (float)(cc >> 1);
            float xfB = x0B + (float)(cc & 1), yfB = y0B + (float)(cc >> 1);
            float mA = (xfA >= 0.f && xfA <= 255.f && yfA >= 0.f && yfA <= 255.f) ? 1.f : 0.f;
            float mB = (xfB >= 0.f && xfB <= 255.f && yfB >= 0.f && yfB <= 255.f) ? 1.f : 0.f;
            int xiA = min(max((int)xfA, 0), 255), yiA = min(max((int)yfA, 0), 255);
            int xiB = min(max((int)xfB, 0), 255), yiB = min(max((int)yfB, 0), 255);
            float4 svA = *(const float4*)(sfb + ((size_t)(yiA * Wv + xiA)) * CH + lane * 4);
            float4 svB = *(const float4*)(sfb + ((size_t)(yiB * Wv + xiB)) * CH + lane * 4);
            float dA = nfA.x*svA.x + nfA.y*svA.y + nfA.z*svA.z + nfA.w*svA.w;
            float dB = nfB.x*svB.x + nfB.y*svB.y + nfB.z*svB.z + nfB.w*svB.w;
            accA += cwA[cc] * mA * dA;
            accB += cwB[cc] * mB * dB;
        }
        lacc += scores[b * Nv + n] * accA + scores[b * Nv + n2] * accB;
    }
    #pragma unroll
    for (int o = 16; o > 0; o >>= 1) lacc += __shfl_down_sync(0xffffffffu, lacc, o);
    if (lane == 0) warpsum[w] = lacc;
    __syncthreads();
    if (t == 0) {
        float s8 = 0.f;
        #pragma unroll
        for (int i = 0; i < 8; i++) s8 += warpsum[i];
        g_logits[b * Sv + s] = s8;
    }
}

// ---------------- K5: softmax, argmax, outputs -----------------------------
__global__ void k_final(float* __restrict__ out,
                        const float* __restrict__ tinit,
                        const float* __restrict__ radius,
                        const float* __restrict__ lscale) {
    int b = blockIdx.x;
    int t = threadIdx.x;   // 256
    __shared__ float sred[256];
    __shared__ int bestI;
    float escale = expf(lscale[0]);
    float L = g_logits[b * Sv + t] * escale;
    sred[t] = L; __syncthreads();
    for (int o = 128; o > 0; o >>= 1) {
        if (t < o) sred[t] = fmaxf(sred[t], sred[t + o]);
        __syncthreads();
    }
    float m = sred[0];
    __syncthreads();
    float e = expf(L - m);
    sred[t] = e; __syncthreads();
    for (int o = 128; o > 0; o >>= 1) {
        if (t < o) sred[t] += sred[t + o];
        __syncthreads();
    }
    float Z = sred[0];
    out[6144 + b * Sv + t] = e / Z;
    if (t == 0) bestI = 1 << 30;
    __syncthreads();
    if (L == m) atomicMin(&bestI, t);
    __syncthreads();
    int bi = bestI;
    float mx = g_cand[((size_t)(b * Sv + bi) * Nv + t) * 2 + 0];
    float my = g_cand[((size_t)(b * Sv + bi) * Nv + t) * 2 + 1];
    out[(b * Nv + t) * 2 + 0] = mx;
    out[(b * Nv + t) * 2 + 1] = my;
    out[2048 + b * Nv + t] =
        (mx >= 0.f && mx < (float)Wv && my >= 0.f && my < (float)Hv) ? 1.f : 0.f;
    float rad = radius[b];
    float sx = -1.f + (float)(t & 15) * (2.f / 15.f);
    float sy = -1.f + (float)(t >> 4) * (2.f / 15.f);
    out[3072 + (b * Sv + t) * 3 + 0] = tinit[b*3+0] + sx * rad;
    out[3072 + (b * Sv + t) * 3 + 1] = tinit[b*3+1] + sy * rad;
    out[3072 + (b * Sv + t) * 3 + 2] = tinit[b*3+2];
}

// ---------------- launch ----------------------------------------------------
extern "C" void kernel_launch(void* const* d_in, const int* in_sizes, int n_in,
                              void* d_out, int out_size) {
    const float* node_coords   = (const float*)d_in[0];
    const float* node_scores   = (const float*)d_in[1];
    const float* node_features = (const float*)d_in[2];
    const float* node_depths   = (const float*)d_in[3];
    const float* K_left        = (const float*)d_in[4];
    const float* R_left        = (const float*)d_in[5];
    const float* t_init        = (const float*)d_in[6];
    const float* sat_featmap   = (const float*)d_in[7];
    const float* K_sat         = (const float*)d_in[8];
    const float* R_sat         = (const float*)d_in[9];
    const float* t_sat         = (const float*)d_in[10];
    const float* radius        = (const float*)d_in[11];
    int off = (n_in >= 18) ? 0 : -1;
    const float* W_node      = (const float*)d_in[13 + off];
    const float* b_node      = (const float*)d_in[14 + off];
    const float* W_sat       = (const float*)d_in[15 + off];
    const float* b_sat       = (const float*)d_in[16 + off];
    const float* logit_scale = (const float*)d_in[17 + off];
    float* out = (float*)d_out;

    cudaFuncSetAttribute(k_sfmma, cudaFuncAttributeMaxDynamicSharedMemorySize, SMEM_K3);

    k_wcvt<<<128, 256>>>(W_sat);
    k_nf<<<128, 128>>>(node_features, W_node, b_node);
    k_pw<<<4, 256>>>(node_coords, node_depths, K_left, R_left, K_sat, R_sat);
    k_sfmma<<<dim3(512, Bv), 256, SMEM_K3>>>(sat_featmap, b_sat);
    k_sample<<<dim3(Sv, Bv), 256>>>(K_sat, R_sat, t_sat, t_init, radius, node_scores);
    k_final<<<Bv, 256>>>(out, t_init, radius, logit_scale);
}